// round 1
// baseline (speedup 1.0000x reference)
#include <cuda_runtime.h>
#include <math.h>

#define S_LEN 2048
#define HID   3584
#define NH    28
#define NKV   4
#define HD    128
#define REP   7   // NH / NKV

// ---------------- scratch (device globals; no allocations allowed) ----------
__device__ float g_q[S_LEN * NH * HD];      // [S, NH, HD]
__device__ float g_k[S_LEN * NKV * HD];     // [S, NKV, HD]
__device__ float g_v[S_LEN * NKV * HD];     // [S, NKV, HD]
__device__ float g_attn[S_LEN * NH * HD];   // [S, NH*HD]
__device__ float g_sin[S_LEN * 64];
__device__ float g_cos[S_LEN * 64];

// ---------------- RoPE sin/cos table (double-precision angles) --------------
__global__ void build_rope_kernel(const int* __restrict__ pos) {
    int idx = blockIdx.x * blockDim.x + threadIdx.x;
    if (idx >= S_LEN * 64) return;
    int i = idx & 63;
    int s = idx >> 6;
    double inv = exp(-((double)i / 64.0) * log(1.0e6));  // theta = 1e6
    double ang = (double)pos[s] * inv;
    g_sin[idx] = (float)sin(ang);
    g_cos[idx] = (float)cos(ang);
}

// ---------------- RoPE application: x[i], x[i+64] pair rotation -------------
__global__ void rope_kernel(float* __restrict__ X, int nheads) {
    int idx = blockIdx.x * blockDim.x + threadIdx.x;
    int total = S_LEN * nheads * 64;
    if (idx >= total) return;
    int i = idx & 63;
    int t = idx >> 6;
    int h = t % nheads;
    int s = t / nheads;
    float sn = g_sin[s * 64 + i];
    float cs = g_cos[s * 64 + i];
    float* p = X + ((size_t)s * nheads + h) * HD;
    float x0 = p[i], x1 = p[i + 64];
    p[i]      = x0 * cs - x1 * sn;
    p[i + 64] = x1 * cs + x0 * sn;
}

// ---------------- SGEMM: C[M,N] = A[M,K] @ B[K,N], all row-major -------------
// 128x128 block tile, BK=8, 256 threads, 8x8 register microtile.
// Assumes M%128==0, N%128==0, K%8==0 (true for all shapes here).
__global__ __launch_bounds__(256, 2)
void sgemm_kernel(const float* __restrict__ A, const float* __restrict__ B,
                  float* __restrict__ C, int M, int N, int K) {
    __shared__ float As[8][132];   // transposed A tile, padded (conflict-free)
    __shared__ float Bs[8][128];

    int tid = threadIdx.x;
    int bm = blockIdx.y, bn = blockIdx.x;
    int tm = tid >> 4, tn = tid & 15;

    const float* Ab = A + (size_t)bm * 128 * K;
    const float* Bb = B + bn * 128;

    int arow = tid >> 1, acol = (tid & 1) * 4;   // A tile 128x8, float4 per thread
    int brow = tid >> 5, bcol = (tid & 31) * 4;  // B tile 8x128, float4 per thread

    float acc[8][8];
#pragma unroll
    for (int i = 0; i < 8; i++)
#pragma unroll
        for (int j = 0; j < 8; j++) acc[i][j] = 0.f;

    for (int k0 = 0; k0 < K; k0 += 8) {
        float4 a4 = *(const float4*)(Ab + (size_t)arow * K + k0 + acol);
        float4 b4 = *(const float4*)(Bb + (size_t)(k0 + brow) * N + bcol);
        As[acol + 0][arow] = a4.x;
        As[acol + 1][arow] = a4.y;
        As[acol + 2][arow] = a4.z;
        As[acol + 3][arow] = a4.w;
        *(float4*)&Bs[brow][bcol] = b4;
        __syncthreads();

#pragma unroll
        for (int kk = 0; kk < 8; kk++) {
            float af[8], bf[8];
            *(float4*)(af)     = *(const float4*)&As[kk][tm * 8];
            *(float4*)(af + 4) = *(const float4*)&As[kk][tm * 8 + 4];
            *(float4*)(bf)     = *(const float4*)&Bs[kk][tn * 8];
            *(float4*)(bf + 4) = *(const float4*)&Bs[kk][tn * 8 + 4];
#pragma unroll
            for (int i = 0; i < 8; i++)
#pragma unroll
                for (int j = 0; j < 8; j++)
                    acc[i][j] += af[i] * bf[j];
        }
        __syncthreads();
    }

#pragma unroll
    for (int i = 0; i < 8; i++) {
        float* crow = C + (size_t)(bm * 128 + tm * 8 + i) * N + bn * 128 + tn * 8;
        *(float4*)(crow)     = make_float4(acc[i][0], acc[i][1], acc[i][2], acc[i][3]);
        *(float4*)(crow + 4) = make_float4(acc[i][4], acc[i][5], acc[i][6], acc[i][7]);
    }
}

// ---------------- Flash attention fp32, causal + pad mask, GQA --------------
// Block: one (64-row q tile, head). 256 threads: 16x16 grid, each thread owns
// 4 q-rows x (4 score cols | 8 output dims). Online softmax, P via smem.
__global__ __launch_bounds__(256)
void flash_kernel(const float* __restrict__ Q, const float* __restrict__ K,
                  const float* __restrict__ V, const int* __restrict__ amask,
                  float* __restrict__ O) {
    extern __shared__ float sh[];
    float* Qs = sh;               // 64 x 132
    float* Ks = Qs + 64 * 132;    // 64 x 132
    float* Vs = Ks + 64 * 132;    // 64 x 132
    float* Ps = Vs + 64 * 132;    // 64 x 68

    int qb = blockIdx.x, h = blockIdx.y;
    int kvh = h / REP;
    int tid = threadIdx.x;
    int trow = tid >> 4, tcol = tid & 15;
    int r0 = trow * 4, c0 = tcol * 4, d0 = tcol * 8;

    // load Q tile (64 x 128) coalesced
    for (int i = tid; i < 2048; i += 256) {
        int rr = i >> 5, c4 = (i & 31) * 4;
        *(float4*)&Qs[rr * 132 + c4] =
            *(const float4*)(Q + ((size_t)(qb * 64 + rr) * NH + h) * HD + c4);
    }

    float m[4], l[4], o[4][8];
#pragma unroll
    for (int i = 0; i < 4; i++) {
        m[i] = -1e30f; l[i] = 0.f;
#pragma unroll
        for (int d = 0; d < 8; d++) o[i][d] = 0.f;
    }
    __syncthreads();

    const float scale = 0.0883883476483184406f;  // 1/sqrt(128)

    for (int kb = 0; kb <= qb; kb++) {
        // load K,V tiles (each 64 x 128) coalesced
        for (int i = tid; i < 2048; i += 256) {
            int rr = i >> 5, c4 = (i & 31) * 4;
            size_t off = ((size_t)(kb * 64 + rr) * NKV + kvh) * HD + c4;
            *(float4*)&Ks[rr * 132 + c4] = *(const float4*)(K + off);
            *(float4*)&Vs[rr * 132 + c4] = *(const float4*)(V + off);
        }
        __syncthreads();

        // S = Q K^T  (4x4 per thread over d=128, float4-vectorized)
        float s[4][4];
#pragma unroll
        for (int i = 0; i < 4; i++)
#pragma unroll
            for (int j = 0; j < 4; j++) s[i][j] = 0.f;

        for (int d4 = 0; d4 < 32; d4++) {
            float4 a[4], b[4];
#pragma unroll
            for (int i = 0; i < 4; i++)
                a[i] = *(const float4*)&Qs[(r0 + i) * 132 + d4 * 4];
#pragma unroll
            for (int j = 0; j < 4; j++)
                b[j] = *(const float4*)&Ks[(c0 + j) * 132 + d4 * 4];
#pragma unroll
            for (int i = 0; i < 4; i++)
#pragma unroll
                for (int j = 0; j < 4; j++)
                    s[i][j] += a[i].x * b[j].x + a[i].y * b[j].y +
                               a[i].z * b[j].z + a[i].w * b[j].w;
        }

        // scale + causal/pad mask
        int grow = qb * 64 + r0, gcol = kb * 64 + c0;
#pragma unroll
        for (int i = 0; i < 4; i++)
#pragma unroll
            for (int j = 0; j < 4; j++) {
                float sv = s[i][j] * scale;
                int gr = grow + i, gc = gcol + j;
                if (gc > gr || __ldg(&amask[gc]) == 0) sv = -1e30f;
                s[i][j] = sv;
            }

        // online softmax (row reductions over 16 lanes)
#pragma unroll
        for (int i = 0; i < 4; i++) {
            float rmax = fmaxf(fmaxf(s[i][0], s[i][1]), fmaxf(s[i][2], s[i][3]));
#pragma unroll
            for (int off = 1; off < 16; off <<= 1)
                rmax = fmaxf(rmax, __shfl_xor_sync(0xffffffffu, rmax, off));
            float mn = fmaxf(m[i], rmax);
            float alpha = __expf(m[i] - mn);
            m[i] = mn;
            float rs = 0.f;
#pragma unroll
            for (int j = 0; j < 4; j++) {
                float p = __expf(s[i][j] - mn);
                s[i][j] = p;
                rs += p;
            }
#pragma unroll
            for (int off = 1; off < 16; off <<= 1)
                rs += __shfl_xor_sync(0xffffffffu, rs, off);
            l[i] = l[i] * alpha + rs;
#pragma unroll
            for (int d = 0; d < 8; d++) o[i][d] *= alpha;
#pragma unroll
            for (int j = 0; j < 4; j++) Ps[(r0 + i) * 68 + c0 + j] = s[i][j];
        }
        __syncthreads();

        // O += P @ V  (thread: 4 rows x 8 dims)
        for (int k = 0; k < 64; k++) {
            float4 v0 = *(const float4*)&Vs[k * 132 + d0];
            float4 v1 = *(const float4*)&Vs[k * 132 + d0 + 4];
#pragma unroll
            for (int i = 0; i < 4; i++) {
                float p = Ps[(r0 + i) * 68 + k];
                o[i][0] += p * v0.x; o[i][1] += p * v0.y;
                o[i][2] += p * v0.z; o[i][3] += p * v0.w;
                o[i][4] += p * v1.x; o[i][5] += p * v1.y;
                o[i][6] += p * v1.z; o[i][7] += p * v1.w;
            }
        }
        __syncthreads();
    }

    // normalize + store (attn layout [S, NH*HD])
#pragma unroll
    for (int i = 0; i < 4; i++) {
        float inv = 1.f / l[i];
        float* op = O + ((size_t)(qb * 64 + r0 + i) * NH + h) * HD + d0;
        *(float4*)(op)     = make_float4(o[i][0] * inv, o[i][1] * inv,
                                         o[i][2] * inv, o[i][3] * inv);
        *(float4*)(op + 4) = make_float4(o[i][4] * inv, o[i][5] * inv,
                                         o[i][6] * inv, o[i][7] * inv);
    }
}

// ---------------- launcher ---------------------------------------------------
extern "C" void kernel_launch(void* const* d_in, const int* in_sizes, int n_in,
                              void* d_out, int out_size) {
    const float* x     = (const float*)d_in[0];  // [1, 2048, 3584]
    const int*   amask = (const int*)  d_in[1];  // [1, 2048]
    const int*   pos   = (const int*)  d_in[2];  // [1, 2048]
    const float* Wq    = (const float*)d_in[3];  // [3584, 3584]
    const float* Wk    = (const float*)d_in[4];  // [3584, 512]
    const float* Wv    = (const float*)d_in[5];  // [3584, 512]
    const float* Wo    = (const float*)d_in[6];  // [3584, 3584]
    float* out = (float*)d_out;                  // [1, 2048, 3584]

    float *qp, *kp, *vp, *ap;
    cudaGetSymbolAddress((void**)&qp, g_q);
    cudaGetSymbolAddress((void**)&kp, g_k);
    cudaGetSymbolAddress((void**)&vp, g_v);
    cudaGetSymbolAddress((void**)&ap, g_attn);

    // 1) RoPE table
    build_rope_kernel<<<(S_LEN * 64 + 255) / 256, 256>>>(pos);

    // 2) QKV projections
    sgemm_kernel<<<dim3(NH * HD / 128, S_LEN / 128), 256>>>(x, Wq, qp, S_LEN, NH * HD, HID);
    sgemm_kernel<<<dim3(NKV * HD / 128, S_LEN / 128), 256>>>(x, Wk, kp, S_LEN, NKV * HD, HID);
    sgemm_kernel<<<dim3(NKV * HD / 128, S_LEN / 128), 256>>>(x, Wv, vp, S_LEN, NKV * HD, HID);

    // 3) RoPE on Q and K
    rope_kernel<<<(S_LEN * NH * 64 + 255) / 256, 256>>>(qp, NH);
    rope_kernel<<<(S_LEN * NKV * 64 + 255) / 256, 256>>>(kp, NKV);

    // 4) flash attention
    size_t flash_smem = (size_t)(3 * 64 * 132 + 64 * 68) * sizeof(float);  // 118784 B
    cudaFuncSetAttribute(flash_kernel, cudaFuncAttributeMaxDynamicSharedMemorySize,
                         (int)flash_smem);
    flash_kernel<<<dim3(S_LEN / 64, NH), 256, flash_smem>>>(qp, kp, vp, amask, ap);

    // 5) O projection -> final output
    sgemm_kernel<<<dim3(HID / 128, S_LEN / 128), 256>>>(ap, Wo, out, S_LEN, HID, HID);
}

// round 2
// speedup vs baseline: 1.1900x; 1.1900x over previous
#include <cuda_runtime.h>
#include <math.h>

#define S_LEN 2048
#define HID   3584
#define NH    28
#define NKV   4
#define HD    128
#define REP   7   // NH / NKV

typedef unsigned long long ull;

// ---------------- scratch (device globals; no allocations allowed) ----------
__device__ float g_q[S_LEN * NH * HD];      // [S, NH, HD]
__device__ float g_k[S_LEN * NKV * HD];     // [S, NKV, HD]
__device__ float g_v[S_LEN * NKV * HD];     // [S, NKV, HD]
__device__ float g_attn[S_LEN * NH * HD];   // [S, NH*HD]
__device__ float g_sin[S_LEN * 64];
__device__ float g_cos[S_LEN * 64];

// ---------------- packed f32x2 helpers --------------------------------------
__device__ __forceinline__ void ffma2(ull& d, ull a, ull b) {
    asm("fma.rn.f32x2 %0, %1, %2, %3;" : "=l"(d) : "l"(a), "l"(b), "l"(d));
}
__device__ __forceinline__ ull fmul2(ull a, ull b) {
    ull d; asm("mul.rn.f32x2 %0, %1, %2;" : "=l"(d) : "l"(a), "l"(b)); return d;
}
__device__ __forceinline__ ull dup2(float x) {
    unsigned int b = __float_as_uint(x);
    ull d; asm("mov.b64 %0, {%1, %1};" : "=l"(d) : "r"(b)); return d;
}
__device__ __forceinline__ float lo2(ull v) { return __uint_as_float((unsigned int)v); }
__device__ __forceinline__ float hi2(ull v) { return __uint_as_float((unsigned int)(v >> 32)); }

// ---------------- RoPE sin/cos table (double-precision angles) --------------
__global__ void build_rope_kernel(const int* __restrict__ pos) {
    int idx = blockIdx.x * blockDim.x + threadIdx.x;
    if (idx >= S_LEN * 64) return;
    int i = idx & 63;
    int s = idx >> 6;
    double inv = exp(-((double)i / 64.0) * log(1.0e6));  // theta = 1e6
    double ang = (double)pos[s] * inv;
    g_sin[idx] = (float)sin(ang);
    g_cos[idx] = (float)cos(ang);
}

// ---------------- RoPE application: x[i], x[i+64] pair rotation -------------
__global__ void rope_kernel(float* __restrict__ X, int nheads) {
    int idx = blockIdx.x * blockDim.x + threadIdx.x;
    int total = S_LEN * nheads * 64;
    if (idx >= total) return;
    int i = idx & 63;
    int t = idx >> 6;
    int h = t % nheads;
    int s = t / nheads;
    float sn = g_sin[s * 64 + i];
    float cs = g_cos[s * 64 + i];
    float* p = X + ((size_t)s * nheads + h) * HD;
    float x0 = p[i], x1 = p[i + 64];
    p[i]      = x0 * cs - x1 * sn;
    p[i + 64] = x1 * cs + x0 * sn;
}

// ---------------- SGEMM core with packed FFMA2 -------------------------------
// 128x128 block tile, BK=8, 256 threads, 8x8 microtile computed as 8x(4 pairs).
// As holds A transposed AND duplicated: As[kk][2r] = As[kk][2r+1] = A[r][kk],
// so register a2[i] = (a_i, a_i) loads with zero extra instructions, and
// b2[jj] = (b_{2jj}, b_{2jj+1}) loads naturally from Bs.
// FUSED=1: QKV fused launch, per-block-column select of B/C among Wq/Wk/Wv.
template <int FUSED>
__global__ __launch_bounds__(256, 2)
void sgemm_kernel(const float* __restrict__ A,
                  const float* __restrict__ B0, const float* __restrict__ B1,
                  const float* __restrict__ B2,
                  float* __restrict__ C0, float* __restrict__ C1,
                  float* __restrict__ C2,
                  int M, int N0, int K) {
    __shared__ float As[8][260];   // duplicated-transposed A tile (16B-aligned stride)
    __shared__ float Bs[8][128];

    int tid = threadIdx.x;
    int bm = blockIdx.y, bn = blockIdx.x;
    int tm = tid >> 4, tn = tid & 15;

    const float* B = B0;
    float* C = C0;
    int ldb = N0, bncol = bn;
    if (FUSED) {
        if (bn >= 28 && bn < 32) { B = B1; C = C1; ldb = NKV * HD; bncol = bn - 28; }
        else if (bn >= 32)       { B = B2; C = C2; ldb = NKV * HD; bncol = bn - 32; }
    }

    const float* Ab = A + (size_t)bm * 128 * K;
    const float* Bb = B + bncol * 128;

    int arow = tid >> 1, acol = (tid & 1) * 4;   // A tile 128x8, float4 per thread
    int brow = tid >> 5, bcol = (tid & 31) * 4;  // B tile 8x128, float4 per thread

    ull acc[8][4];
#pragma unroll
    for (int i = 0; i < 8; i++)
#pragma unroll
        for (int j = 0; j < 4; j++) acc[i][j] = 0ULL;

    for (int k0 = 0; k0 < K; k0 += 8) {
        float4 a4 = *(const float4*)(Ab + (size_t)arow * K + k0 + acol);
        float4 b4 = *(const float4*)(Bb + (size_t)(k0 + brow) * ldb + bcol);
        *(float2*)&As[acol + 0][2 * arow] = make_float2(a4.x, a4.x);
        *(float2*)&As[acol + 1][2 * arow] = make_float2(a4.y, a4.y);
        *(float2*)&As[acol + 2][2 * arow] = make_float2(a4.z, a4.z);
        *(float2*)&As[acol + 3][2 * arow] = make_float2(a4.w, a4.w);
        *(float4*)&Bs[brow][bcol] = b4;
        __syncthreads();

#pragma unroll
        for (int kk = 0; kk < 8; kk++) {
            ull a2[8], b2[4];
#pragma unroll
            for (int q = 0; q < 4; q++) {
                ulonglong2 t = *(const ulonglong2*)&As[kk][tm * 16 + q * 4];
                a2[2 * q]     = t.x;
                a2[2 * q + 1] = t.y;
            }
            {
                ulonglong2 t0 = *(const ulonglong2*)&Bs[kk][tn * 8];
                ulonglong2 t1 = *(const ulonglong2*)&Bs[kk][tn * 8 + 4];
                b2[0] = t0.x; b2[1] = t0.y; b2[2] = t1.x; b2[3] = t1.y;
            }
#pragma unroll
            for (int i = 0; i < 8; i++)
#pragma unroll
                for (int j = 0; j < 4; j++)
                    ffma2(acc[i][j], a2[i], b2[j]);
        }
        __syncthreads();
    }

#pragma unroll
    for (int i = 0; i < 8; i++) {
        float* crow = C + (size_t)(bm * 128 + tm * 8 + i) * ldb + bncol * 128 + tn * 8;
        *(float4*)(crow)     = *(float4*)&acc[i][0];
        *(float4*)(crow + 4) = *(float4*)&acc[i][2];
    }
}

// ---------------- Flash attention fp32 (FFMA2), causal + pad mask, GQA ------
// Block: one (64-row q tile, head). 256 threads: 16x16, each thread owns
// 4 q-rows x (4 score cols | 8 output dims). Online softmax; P staged in smem
// pre-duplicated as 64-bit (p,p) pairs for packed PV.
__global__ __launch_bounds__(256)
void flash_kernel(const float* __restrict__ Q, const float* __restrict__ K,
                  const float* __restrict__ V, const int* __restrict__ amask,
                  float* __restrict__ O) {
    extern __shared__ float sh[];
    float* Qs = sh;               // 64 x 132
    float* Ks = Qs + 64 * 132;    // 64 x 132
    float* Vs = Ks + 64 * 132;    // 64 x 132
    ull*   Psd = (ull*)(Vs + 64 * 132);  // 64 x 66 packed (p,p)

    int qb = (gridDim.x - 1) - blockIdx.x;  // heavy tiles scheduled first
    int h = blockIdx.y;
    int kvh = h / REP;
    int tid = threadIdx.x;
    int trow = tid >> 4, tcol = tid & 15;
    int r0 = trow * 4, c0 = tcol * 4, d0 = tcol * 8;

    // load Q tile (64 x 128) coalesced
    for (int i = tid; i < 2048; i += 256) {
        int rr = i >> 5, c4 = (i & 31) * 4;
        *(float4*)&Qs[rr * 132 + c4] =
            *(const float4*)(Q + ((size_t)(qb * 64 + rr) * NH + h) * HD + c4);
    }

    float m[4], l[4];
    ull o2[4][4];
#pragma unroll
    for (int i = 0; i < 4; i++) {
        m[i] = -1e30f; l[i] = 0.f;
#pragma unroll
        for (int d = 0; d < 4; d++) o2[i][d] = 0ULL;
    }
    __syncthreads();

    const float scale = 0.0883883476483184406f;  // 1/sqrt(128)

    for (int kb = 0; kb <= qb; kb++) {
        // load K,V tiles (each 64 x 128) coalesced
        for (int i = tid; i < 2048; i += 256) {
            int rr = i >> 5, c4 = (i & 31) * 4;
            size_t off = ((size_t)(kb * 64 + rr) * NKV + kvh) * HD + c4;
            *(float4*)&Ks[rr * 132 + c4] = *(const float4*)(K + off);
            *(float4*)&Vs[rr * 132 + c4] = *(const float4*)(V + off);
        }
        __syncthreads();

        // S = Q K^T, packed along d (4x4 per thread)
        ull s2[4][4];
#pragma unroll
        for (int i = 0; i < 4; i++)
#pragma unroll
            for (int j = 0; j < 4; j++) s2[i][j] = 0ULL;

        for (int d4 = 0; d4 < 32; d4++) {
            ull a[4][2], b[4][2];
#pragma unroll
            for (int i = 0; i < 4; i++) {
                ulonglong2 t = *(const ulonglong2*)&Qs[(r0 + i) * 132 + d4 * 4];
                a[i][0] = t.x; a[i][1] = t.y;
            }
#pragma unroll
            for (int j = 0; j < 4; j++) {
                ulonglong2 t = *(const ulonglong2*)&Ks[(c0 + j) * 132 + d4 * 4];
                b[j][0] = t.x; b[j][1] = t.y;
            }
#pragma unroll
            for (int i = 0; i < 4; i++)
#pragma unroll
                for (int j = 0; j < 4; j++) {
                    ffma2(s2[i][j], a[i][0], b[j][0]);
                    ffma2(s2[i][j], a[i][1], b[j][1]);
                }
        }

        // reduce pairs, scale + causal/pad mask
        float s[4][4];
        int grow = qb * 64 + r0, gcol = kb * 64 + c0;
#pragma unroll
        for (int i = 0; i < 4; i++)
#pragma unroll
            for (int j = 0; j < 4; j++) {
                float sv = (lo2(s2[i][j]) + hi2(s2[i][j])) * scale;
                int gr = grow + i, gc = gcol + j;
                if (gc > gr || __ldg(&amask[gc]) == 0) sv = -1e30f;
                s[i][j] = sv;
            }

        // online softmax (row reductions over 16 lanes)
#pragma unroll
        for (int i = 0; i < 4; i++) {
            float rmax = fmaxf(fmaxf(s[i][0], s[i][1]), fmaxf(s[i][2], s[i][3]));
#pragma unroll
            for (int off = 1; off < 16; off <<= 1)
                rmax = fmaxf(rmax, __shfl_xor_sync(0xffffffffu, rmax, off));
            float mn = fmaxf(m[i], rmax);
            float alpha = __expf(m[i] - mn);
            m[i] = mn;
            float rs = 0.f;
#pragma unroll
            for (int j = 0; j < 4; j++) {
                float p = __expf(s[i][j] - mn);
                s[i][j] = p;
                rs += p;
            }
#pragma unroll
            for (int off = 1; off < 16; off <<= 1)
                rs += __shfl_xor_sync(0xffffffffu, rs, off);
            l[i] = l[i] * alpha + rs;
            ull ad = dup2(alpha);
#pragma unroll
            for (int d = 0; d < 4; d++) o2[i][d] = fmul2(o2[i][d], ad);
#pragma unroll
            for (int j = 0; j < 4; j++)
                Psd[(r0 + i) * 66 + c0 + j] = dup2(s[i][j]);
        }
        __syncthreads();

        // O += P @ V  (thread: 4 rows x 4 dim-pairs, packed along dims)
        for (int k = 0; k < 64; k++) {
            ulonglong2 v0 = *(const ulonglong2*)&Vs[k * 132 + d0];
            ulonglong2 v1 = *(const ulonglong2*)&Vs[k * 132 + d0 + 4];
#pragma unroll
            for (int i = 0; i < 4; i++) {
                ull pd = Psd[(r0 + i) * 66 + k];
                ffma2(o2[i][0], pd, v0.x);
                ffma2(o2[i][1], pd, v0.y);
                ffma2(o2[i][2], pd, v1.x);
                ffma2(o2[i][3], pd, v1.y);
            }
        }
        __syncthreads();
    }

    // normalize + store (attn layout [S, NH*HD])
#pragma unroll
    for (int i = 0; i < 4; i++) {
        float inv = 1.f / l[i];
        float* op = O + ((size_t)(qb * 64 + r0 + i) * NH + h) * HD + d0;
        *(float4*)(op)     = make_float4(lo2(o2[i][0]) * inv, hi2(o2[i][0]) * inv,
                                         lo2(o2[i][1]) * inv, hi2(o2[i][1]) * inv);
        *(float4*)(op + 4) = make_float4(lo2(o2[i][2]) * inv, hi2(o2[i][2]) * inv,
                                         lo2(o2[i][3]) * inv, hi2(o2[i][3]) * inv);
    }
}

// ---------------- launcher ---------------------------------------------------
extern "C" void kernel_launch(void* const* d_in, const int* in_sizes, int n_in,
                              void* d_out, int out_size) {
    const float* x     = (const float*)d_in[0];  // [1, 2048, 3584]
    const int*   amask = (const int*)  d_in[1];  // [1, 2048]
    const int*   pos   = (const int*)  d_in[2];  // [1, 2048]
    const float* Wq    = (const float*)d_in[3];  // [3584, 3584]
    const float* Wk    = (const float*)d_in[4];  // [3584, 512]
    const float* Wv    = (const float*)d_in[5];  // [3584, 512]
    const float* Wo    = (const float*)d_in[6];  // [3584, 3584]
    float* out = (float*)d_out;                  // [1, 2048, 3584]

    float *qp, *kp, *vp, *ap;
    cudaGetSymbolAddress((void**)&qp, g_q);
    cudaGetSymbolAddress((void**)&kp, g_k);
    cudaGetSymbolAddress((void**)&vp, g_v);
    cudaGetSymbolAddress((void**)&ap, g_attn);

    // 1) RoPE table
    build_rope_kernel<<<(S_LEN * 64 + 255) / 256, 256>>>(pos);

    // 2) fused QKV projection: 36 column blocks (28 Q | 4 K | 4 V) x 16 row blocks
    sgemm_kernel<1><<<dim3(36, S_LEN / 128), 256>>>(
        x, Wq, Wk, Wv, qp, kp, vp, S_LEN, NH * HD, HID);

    // 3) RoPE on Q and K
    rope_kernel<<<(S_LEN * NH * 64 + 255) / 256, 256>>>(qp, NH);
    rope_kernel<<<(S_LEN * NKV * 64 + 255) / 256, 256>>>(kp, NKV);

    // 4) flash attention
    size_t flash_smem = (size_t)(3 * 64 * 132) * sizeof(float)
                      + (size_t)(64 * 66) * sizeof(ull);  // 135168 B
    cudaFuncSetAttribute(flash_kernel, cudaFuncAttributeMaxDynamicSharedMemorySize,
                         (int)flash_smem);
    flash_kernel<<<dim3(S_LEN / 64, NH), 256, flash_smem>>>(qp, kp, vp, amask, ap);

    // 5) O projection -> final output
    sgemm_kernel<0><<<dim3(HID / 128, S_LEN / 128), 256>>>(
        ap, Wo, nullptr, nullptr, out, nullptr, nullptr, S_LEN, HID, HID);
}

// round 3
// speedup vs baseline: 1.5440x; 1.2975x over previous
#include <cuda_runtime.h>
#include <math.h>

#define S_LEN 2048
#define HID   3584
#define NH    28
#define NKV   4
#define HD    128
#define REP   7   // NH / NKV

typedef unsigned long long ull;

// ---------------- scratch (device globals; no allocations allowed) ----------
__device__ float g_q[S_LEN * NH * HD];      // [S, NH, HD]
__device__ float g_k[S_LEN * NKV * HD];     // [S, NKV, HD]
__device__ float g_v[S_LEN * NKV * HD];     // [S, NKV, HD]
__device__ float g_attn[S_LEN * NH * HD];   // [S, NH*HD]
__device__ float g_sin[S_LEN * 64];
__device__ float g_cos[S_LEN * 64];

// ---------------- packed f32x2 helpers --------------------------------------
__device__ __forceinline__ void ffma2(ull& d, ull a, ull b) {
    asm("fma.rn.f32x2 %0, %1, %2, %3;" : "=l"(d) : "l"(a), "l"(b), "l"(d));
}
__device__ __forceinline__ ull fmul2(ull a, ull b) {
    ull d; asm("mul.rn.f32x2 %0, %1, %2;" : "=l"(d) : "l"(a), "l"(b)); return d;
}
__device__ __forceinline__ ull dup2(float x) {
    unsigned int b = __float_as_uint(x);
    ull d; asm("mov.b64 %0, {%1, %1};" : "=l"(d) : "r"(b)); return d;
}
__device__ __forceinline__ float lo2(ull v) { return __uint_as_float((unsigned int)v); }
__device__ __forceinline__ float hi2(ull v) { return __uint_as_float((unsigned int)(v >> 32)); }

// ---------------- RoPE sin/cos table (double-precision angles) --------------
__global__ void build_rope_kernel(const int* __restrict__ pos) {
    int idx = blockIdx.x * blockDim.x + threadIdx.x;
    if (idx >= S_LEN * 64) return;
    int i = idx & 63;
    int s = idx >> 6;
    double inv = exp(-((double)i / 64.0) * log(1.0e6));  // theta = 1e6
    double ang = (double)pos[s] * inv;
    g_sin[idx] = (float)sin(ang);
    g_cos[idx] = (float)cos(ang);
}

// ---------------- RoPE application: x[i], x[i+64] pair rotation -------------
__global__ void rope_kernel(float* __restrict__ X, int nheads) {
    int idx = blockIdx.x * blockDim.x + threadIdx.x;
    int total = S_LEN * nheads * 64;
    if (idx >= total) return;
    int i = idx & 63;
    int t = idx >> 6;
    int h = t % nheads;
    int s = t / nheads;
    float sn = g_sin[s * 64 + i];
    float cs = g_cos[s * 64 + i];
    float* p = X + ((size_t)s * nheads + h) * HD;
    float x0 = p[i], x1 = p[i + 64];
    p[i]      = x0 * cs - x1 * sn;
    p[i + 64] = x1 * cs + x0 * sn;
}

// ---------------- SGEMM v3: row-pair-packed FFMA2, double-buffered ----------
// 128x128 tile, BK=8, 256 threads, 8x8 microtile as 4 row-pairs x 8 cols.
// A stored transposed (NOT duplicated): a-frag = (A[2i][k],A[2i+1][k]) native.
// B scalars dup'd via 1 mov each (ALU pipe, overlaps FMA pipe).
// Per kk per thread: 4 LDS.128 + 8 mov + 32 FFMA2  -> fma-bound.
template <int FUSED>
__global__ __launch_bounds__(256, 2)
void sgemm_kernel(const float* __restrict__ A,
                  const float* __restrict__ B0, const float* __restrict__ B1,
                  const float* __restrict__ B2,
                  float* __restrict__ C0, float* __restrict__ C1,
                  float* __restrict__ C2,
                  int M, int N0, int K) {
    __shared__ float Ats[2][8][132];   // [buf][k][row], transposed A
    __shared__ float Bs [2][8][128];   // [buf][k][col]

    int tid = threadIdx.x;
    int bm = blockIdx.y, bn = blockIdx.x;
    int tm = tid >> 4, tn = tid & 15;

    const float* B = B0;
    float* C = C0;
    int ldb = N0, bncol = bn;
    if (FUSED) {
        if (bn >= 28 && bn < 32) { B = B1; C = C1; ldb = NKV * HD; bncol = bn - 28; }
        else if (bn >= 32)       { B = B2; C = C2; ldb = NKV * HD; bncol = bn - 32; }
    }

    const float* Ab = A + (size_t)bm * 128 * K;
    const float* Bb = B + bncol * 128;

    int arow = tid >> 1, acol = (tid & 1) * 4;   // A tile 128x8, one float4/thread
    int brow = tid >> 5, bcol = (tid & 31) * 4;  // B tile 8x128, one float4/thread

    // prologue: tile 0 -> buffer 0
    {
        float4 a4 = *(const float4*)(Ab + (size_t)arow * K + acol);
        float4 b4 = *(const float4*)(Bb + (size_t)brow * ldb + bcol);
        Ats[0][acol + 0][arow] = a4.x;
        Ats[0][acol + 1][arow] = a4.y;
        Ats[0][acol + 2][arow] = a4.z;
        Ats[0][acol + 3][arow] = a4.w;
        *(float4*)&Bs[0][brow][bcol] = b4;
    }
    __syncthreads();

    ull acc[4][8];   // [row-pair][col]
#pragma unroll
    for (int p = 0; p < 4; p++)
#pragma unroll
        for (int j = 0; j < 8; j++) acc[p][j] = 0ULL;

    int nit = K >> 3;
    for (int it = 0; it < nit; ++it) {
        int buf = it & 1;
        float4 a4, b4;
        bool more = (it + 1 < nit);
        if (more) {
            int k0 = (it + 1) << 3;
            a4 = *(const float4*)(Ab + (size_t)arow * K + k0 + acol);
            b4 = *(const float4*)(Bb + (size_t)(k0 + brow) * ldb + bcol);
        }

#pragma unroll
        for (int kk = 0; kk < 8; kk++) {
            ulonglong2 A0 = *(const ulonglong2*)&Ats[buf][kk][tm * 8];
            ulonglong2 A1 = *(const ulonglong2*)&Ats[buf][kk][tm * 8 + 4];
            float4 Bv0 = *(const float4*)&Bs[buf][kk][tn * 8];
            float4 Bv1 = *(const float4*)&Bs[buf][kk][tn * 8 + 4];
            ull ap[4] = {A0.x, A0.y, A1.x, A1.y};
            ull bd[8] = {dup2(Bv0.x), dup2(Bv0.y), dup2(Bv0.z), dup2(Bv0.w),
                         dup2(Bv1.x), dup2(Bv1.y), dup2(Bv1.z), dup2(Bv1.w)};
#pragma unroll
            for (int p = 0; p < 4; p++)
#pragma unroll
                for (int j = 0; j < 8; j++)
                    ffma2(acc[p][j], ap[p], bd[j]);
        }

        if (more) {
            int nb = buf ^ 1;
            Ats[nb][acol + 0][arow] = a4.x;
            Ats[nb][acol + 1][arow] = a4.y;
            Ats[nb][acol + 2][arow] = a4.z;
            Ats[nb][acol + 3][arow] = a4.w;
            *(float4*)&Bs[nb][brow][bcol] = b4;
        }
        __syncthreads();
    }

    // store: acc[p] holds rows (2p, 2p+1) in (lo, hi)
#pragma unroll
    for (int p = 0; p < 4; p++) {
        int r = bm * 128 + tm * 8 + 2 * p;
        float* cr = C + (size_t)r * ldb + bncol * 128 + tn * 8;
        *(float4*)(cr)     = make_float4(lo2(acc[p][0]), lo2(acc[p][1]),
                                         lo2(acc[p][2]), lo2(acc[p][3]));
        *(float4*)(cr + 4) = make_float4(lo2(acc[p][4]), lo2(acc[p][5]),
                                         lo2(acc[p][6]), lo2(acc[p][7]));
        *(float4*)(cr + ldb)     = make_float4(hi2(acc[p][0]), hi2(acc[p][1]),
                                               hi2(acc[p][2]), hi2(acc[p][3]));
        *(float4*)(cr + ldb + 4) = make_float4(hi2(acc[p][4]), hi2(acc[p][5]),
                                               hi2(acc[p][6]), hi2(acc[p][7]));
    }
}

// ---------------- Flash attention v3: q-tile 128, k-tile 64, 8x4 microtile --
// 256 threads: tm=row-group (8 rows each), tn: 4 score cols / 8 output dims.
// QK dot-packed along d; PV dup-packed along dims (Ps staged as (p,p) pairs).
__global__ __launch_bounds__(256)
void flash_kernel(const float* __restrict__ Q, const float* __restrict__ K,
                  const float* __restrict__ V, const int* __restrict__ amask,
                  float* __restrict__ O) {
    extern __shared__ float sh[];
    float* Qs = sh;                     // 128 x 132
    float* Ks = Qs + 128 * 132;         // 64 x 132
    float* Vs = Ks + 64 * 132;          // 64 x 132
    ull*   Psd = (ull*)(Vs + 64 * 132); // 128 x 66 packed (p,p)

    int qb = (gridDim.x - 1) - blockIdx.x;  // heavy tiles first
    int h = blockIdx.y;
    int kvh = h / REP;
    int tid = threadIdx.x;
    int tm = tid >> 4, tn = tid & 15;
    int r0 = tm * 8, c0 = tn * 4, d0 = tn * 8;

    // load Q tile (128 x 128) coalesced
    for (int i = tid; i < 128 * 32; i += 256) {
        int rr = i >> 5, c4 = (i & 31) * 4;
        *(float4*)&Qs[rr * 132 + c4] =
            *(const float4*)(Q + ((size_t)(qb * 128 + rr) * NH + h) * HD + c4);
    }

    float m[8], l[8];
    ull o2[8][4];
#pragma unroll
    for (int i = 0; i < 8; i++) {
        m[i] = -1e30f; l[i] = 0.f;
#pragma unroll
        for (int d = 0; d < 4; d++) o2[i][d] = 0ULL;
    }
    __syncthreads();

    const float scale = 0.0883883476483184406f;  // 1/sqrt(128)
    int kbmax = 2 * qb + 1;

    for (int kb = 0; kb <= kbmax; kb++) {
        // load K,V tiles (each 64 x 128) coalesced
        for (int i = tid; i < 64 * 32; i += 256) {
            int rr = i >> 5, c4 = (i & 31) * 4;
            size_t off = ((size_t)(kb * 64 + rr) * NKV + kvh) * HD + c4;
            *(float4*)&Ks[rr * 132 + c4] = *(const float4*)(K + off);
            *(float4*)&Vs[rr * 132 + c4] = *(const float4*)(V + off);
        }
        __syncthreads();

        // S = Q K^T, dot-packed along d (8x4 per thread)
        ull s2[8][4];
#pragma unroll
        for (int i = 0; i < 8; i++)
#pragma unroll
            for (int j = 0; j < 4; j++) s2[i][j] = 0ULL;

#pragma unroll 4
        for (int d4 = 0; d4 < 32; d4++) {
            ull kb0[4], kb1[4];
#pragma unroll
            for (int j = 0; j < 4; j++) {
                ulonglong2 t = *(const ulonglong2*)&Ks[(c0 + j) * 132 + d4 * 4];
                kb0[j] = t.x; kb1[j] = t.y;
            }
#pragma unroll
            for (int i = 0; i < 8; i++) {
                ulonglong2 qa = *(const ulonglong2*)&Qs[(r0 + i) * 132 + d4 * 4];
#pragma unroll
                for (int j = 0; j < 4; j++) {
                    ffma2(s2[i][j], qa.x, kb0[j]);
                    ffma2(s2[i][j], qa.y, kb1[j]);
                }
            }
        }

        // reduce pairs, scale + causal/pad mask
        int grow = qb * 128 + r0, gcol = kb * 64 + c0;
        int mk[4];
#pragma unroll
        for (int j = 0; j < 4; j++) mk[j] = __ldg(&amask[gcol + j]);

        float s[8][4];
#pragma unroll
        for (int i = 0; i < 8; i++)
#pragma unroll
            for (int j = 0; j < 4; j++) {
                float sv = (lo2(s2[i][j]) + hi2(s2[i][j])) * scale;
                if (gcol + j > grow + i || mk[j] == 0) sv = -1e30f;
                s[i][j] = sv;
            }

        // online softmax (row reductions over 16 lanes)
#pragma unroll
        for (int i = 0; i < 8; i++) {
            float rmax = fmaxf(fmaxf(s[i][0], s[i][1]), fmaxf(s[i][2], s[i][3]));
#pragma unroll
            for (int off = 1; off < 16; off <<= 1)
                rmax = fmaxf(rmax, __shfl_xor_sync(0xffffffffu, rmax, off));
            float mn = fmaxf(m[i], rmax);
            float alpha = __expf(m[i] - mn);
            m[i] = mn;
            float rs = 0.f;
#pragma unroll
            for (int j = 0; j < 4; j++) {
                float p = __expf(s[i][j] - mn);
                s[i][j] = p;
                rs += p;
            }
#pragma unroll
            for (int off = 1; off < 16; off <<= 1)
                rs += __shfl_xor_sync(0xffffffffu, rs, off);
            l[i] = l[i] * alpha + rs;
            ull ad = dup2(alpha);
#pragma unroll
            for (int d = 0; d < 4; d++) o2[i][d] = fmul2(o2[i][d], ad);
#pragma unroll
            for (int j = 0; j < 4; j++)
                Psd[(r0 + i) * 66 + c0 + j] = dup2(s[i][j]);
        }
        __syncthreads();

        // O += P @ V  (thread: 8 rows x 4 dim-pairs)
#pragma unroll 2
        for (int c = 0; c < 64; c++) {
            ulonglong2 v0 = *(const ulonglong2*)&Vs[c * 132 + d0];
            ulonglong2 v1 = *(const ulonglong2*)&Vs[c * 132 + d0 + 4];
#pragma unroll
            for (int i = 0; i < 8; i++) {
                ull pd = Psd[(r0 + i) * 66 + c];
                ffma2(o2[i][0], pd, v0.x);
                ffma2(o2[i][1], pd, v0.y);
                ffma2(o2[i][2], pd, v1.x);
                ffma2(o2[i][3], pd, v1.y);
            }
        }
        __syncthreads();
    }

    // normalize + store (attn layout [S, NH*HD])
#pragma unroll
    for (int i = 0; i < 8; i++) {
        float inv = 1.f / l[i];
        float* op = O + ((size_t)(qb * 128 + r0 + i) * NH + h) * HD + d0;
        *(float4*)(op)     = make_float4(lo2(o2[i][0]) * inv, hi2(o2[i][0]) * inv,
                                         lo2(o2[i][1]) * inv, hi2(o2[i][1]) * inv);
        *(float4*)(op + 4) = make_float4(lo2(o2[i][2]) * inv, hi2(o2[i][2]) * inv,
                                         lo2(o2[i][3]) * inv, hi2(o2[i][3]) * inv);
    }
}

// ---------------- launcher ---------------------------------------------------
extern "C" void kernel_launch(void* const* d_in, const int* in_sizes, int n_in,
                              void* d_out, int out_size) {
    const float* x     = (const float*)d_in[0];  // [1, 2048, 3584]
    const int*   amask = (const int*)  d_in[1];  // [1, 2048]
    const int*   pos   = (const int*)  d_in[2];  // [1, 2048]
    const float* Wq    = (const float*)d_in[3];  // [3584, 3584]
    const float* Wk    = (const float*)d_in[4];  // [3584, 512]
    const float* Wv    = (const float*)d_in[5];  // [3584, 512]
    const float* Wo    = (const float*)d_in[6];  // [3584, 3584]
    float* out = (float*)d_out;                  // [1, 2048, 3584]

    float *qp, *kp, *vp, *ap;
    cudaGetSymbolAddress((void**)&qp, g_q);
    cudaGetSymbolAddress((void**)&kp, g_k);
    cudaGetSymbolAddress((void**)&vp, g_v);
    cudaGetSymbolAddress((void**)&ap, g_attn);

    // 1) RoPE table
    build_rope_kernel<<<(S_LEN * 64 + 255) / 256, 256>>>(pos);

    // 2) fused QKV projection: 36 column blocks (28 Q | 4 K | 4 V) x 16 row blocks
    sgemm_kernel<1><<<dim3(36, S_LEN / 128), 256>>>(
        x, Wq, Wk, Wv, qp, kp, vp, S_LEN, NH * HD, HID);

    // 3) RoPE on Q and K
    rope_kernel<<<(S_LEN * NH * 64 + 255) / 256, 256>>>(qp, NH);
    rope_kernel<<<(S_LEN * NKV * 64 + 255) / 256, 256>>>(kp, NKV);

    // 4) flash attention: q-tile 128, 16 x 28 grid
    size_t flash_smem = (size_t)(128 * 132 + 64 * 132 + 64 * 132) * sizeof(float)
                      + (size_t)(128 * 66) * sizeof(ull);  // 202752 B
    cudaFuncSetAttribute(flash_kernel, cudaFuncAttributeMaxDynamicSharedMemorySize,
                         (int)flash_smem);
    flash_kernel<<<dim3(S_LEN / 128, NH), 256, flash_smem>>>(qp, kp, vp, amask, ap);

    // 5) O projection -> final output
    sgemm_kernel<0><<<dim3(HID / 128, S_LEN / 128), 256>>>(
        ap, Wo, nullptr, nullptr, out, nullptr, nullptr, S_LEN, HID, HID);
}

// round 5
// speedup vs baseline: 2.6395x; 1.7095x over previous
#include <cuda_runtime.h>
#include <cuda_fp16.h>
#include <math.h>
#include <cstdint>

#define S_LEN 2048
#define HID   3584
#define NH    28
#define NKV   4
#define HD    128
#define REP   7   // NH / NKV

typedef unsigned long long ull;

// ---------------- scratch (device globals; no allocations allowed) ----------
__device__ float g_q[S_LEN * NH * HD];      // [S, NH, HD]
__device__ float g_k[S_LEN * NKV * HD];     // [S, NKV, HD]
__device__ float g_v[S_LEN * NKV * HD];     // [S, NKV, HD]
__device__ float g_attn[S_LEN * NH * HD];   // [S, NH*HD]
__device__ float g_sin[S_LEN * 64];
__device__ float g_cos[S_LEN * 64];

// fp16 hi/lo splits
__device__ __align__(16) __half g_x_hi[S_LEN * HID];
__device__ __align__(16) __half g_x_lo[S_LEN * HID];
__device__ __align__(16) __half g_wq_hi[HID * NH * HD];
__device__ __align__(16) __half g_wq_lo[HID * NH * HD];
__device__ __align__(16) __half g_wk_hi[HID * NKV * HD];
__device__ __align__(16) __half g_wk_lo[HID * NKV * HD];
__device__ __align__(16) __half g_wv_hi[HID * NKV * HD];
__device__ __align__(16) __half g_wv_lo[HID * NKV * HD];
__device__ __align__(16) __half g_wo_hi[NH * HD * HID];
__device__ __align__(16) __half g_wo_lo[NH * HD * HID];
__device__ __align__(16) __half g_a_hi[S_LEN * NH * HD];
__device__ __align__(16) __half g_a_lo[S_LEN * NH * HD];

// ---------------- packed f32x2 helpers (flash kernel) -----------------------
__device__ __forceinline__ void ffma2(ull& d, ull a, ull b) {
    asm("fma.rn.f32x2 %0, %1, %2, %3;" : "=l"(d) : "l"(a), "l"(b), "l"(d));
}
__device__ __forceinline__ ull fmul2(ull a, ull b) {
    ull d; asm("mul.rn.f32x2 %0, %1, %2;" : "=l"(d) : "l"(a), "l"(b)); return d;
}
__device__ __forceinline__ ull dup2(float x) {
    unsigned int b = __float_as_uint(x);
    ull d; asm("mov.b64 %0, {%1, %1};" : "=l"(d) : "r"(b)); return d;
}
__device__ __forceinline__ float lo2(ull v) { return __uint_as_float((unsigned int)v); }
__device__ __forceinline__ float hi2(ull v) { return __uint_as_float((unsigned int)(v >> 32)); }

// ---------------- HMMA helpers (base-target instructions only) --------------
__device__ __forceinline__ uint32_t smem_u32(const void* p) {
    uint32_t a;
    asm("{ .reg .u64 t; cvta.to.shared.u64 t, %1; cvt.u32.u64 %0, t; }"
        : "=r"(a) : "l"(p));
    return a;
}
__device__ __forceinline__ void ldsm_x4(uint32_t* r, uint32_t addr) {
    asm volatile("ldmatrix.sync.aligned.m8n8.x4.shared.b16 {%0,%1,%2,%3}, [%4];"
        : "=r"(r[0]), "=r"(r[1]), "=r"(r[2]), "=r"(r[3]) : "r"(addr));
}
__device__ __forceinline__ void ldsm_x4t(uint32_t* r, uint32_t addr) {
    asm volatile("ldmatrix.sync.aligned.m8n8.x4.trans.shared.b16 {%0,%1,%2,%3}, [%4];"
        : "=r"(r[0]), "=r"(r[1]), "=r"(r[2]), "=r"(r[3]) : "r"(addr));
}
__device__ __forceinline__ void mma16816(float* d, const uint32_t* a,
                                         uint32_t b0, uint32_t b1) {
    asm volatile(
        "mma.sync.aligned.m16n8k16.row.col.f32.f16.f16.f32 "
        "{%0,%1,%2,%3}, {%4,%5,%6,%7}, {%8,%9}, {%0,%1,%2,%3};"
        : "+f"(d[0]), "+f"(d[1]), "+f"(d[2]), "+f"(d[3])
        : "r"(a[0]), "r"(a[1]), "r"(a[2]), "r"(a[3]), "r"(b0), "r"(b1));
}
#define CPASYNC16(dst, src) \
    asm volatile("cp.async.cg.shared.global [%0], [%1], 16;" \
                 :: "r"(dst), "l"(src) : "memory")
#define CP_COMMIT() asm volatile("cp.async.commit_group;" ::: "memory")
#define CP_WAIT1()  asm volatile("cp.async.wait_group 1;" ::: "memory")
#define CP_WAIT0()  asm volatile("cp.async.wait_group 0;" ::: "memory")

// ---------------- fp32 -> fp16 hi/lo split -----------------------------------
__global__ void split_kernel(const float* __restrict__ src,
                             __half* __restrict__ hi,
                             __half* __restrict__ lo, int n4) {
    int i = blockIdx.x * blockDim.x + threadIdx.x;
    if (i >= n4) return;
    float4 v = ((const float4*)src)[i];
    __half h0 = __float2half_rn(v.x), h1 = __float2half_rn(v.y);
    __half h2 = __float2half_rn(v.z), h3 = __float2half_rn(v.w);
    __half l0 = __float2half_rn(v.x - __half2float(h0));
    __half l1 = __float2half_rn(v.y - __half2float(h1));
    __half l2 = __float2half_rn(v.z - __half2float(h2));
    __half l3 = __float2half_rn(v.w - __half2float(h3));
    ((uint2*)hi)[i] = make_uint2(
        (uint32_t)__half_as_ushort(h0) | ((uint32_t)__half_as_ushort(h1) << 16),
        (uint32_t)__half_as_ushort(h2) | ((uint32_t)__half_as_ushort(h3) << 16));
    ((uint2*)lo)[i] = make_uint2(
        (uint32_t)__half_as_ushort(l0) | ((uint32_t)__half_as_ushort(l1) << 16),
        (uint32_t)__half_as_ushort(l2) | ((uint32_t)__half_as_ushort(l3) << 16));
}

// ---------------- RoPE sin/cos table (double-precision angles) --------------
__global__ void build_rope_kernel(const int* __restrict__ pos) {
    int idx = blockIdx.x * blockDim.x + threadIdx.x;
    if (idx >= S_LEN * 64) return;
    int i = idx & 63;
    int s = idx >> 6;
    double inv = exp(-((double)i / 64.0) * log(1.0e6));  // theta = 1e6
    double ang = (double)pos[s] * inv;
    g_sin[idx] = (float)sin(ang);
    g_cos[idx] = (float)cos(ang);
}

// ---------------- RoPE application: x[i], x[i+64] pair rotation -------------
__global__ void rope_kernel(float* __restrict__ X, int nheads) {
    int idx = blockIdx.x * blockDim.x + threadIdx.x;
    int total = S_LEN * nheads * 64;
    if (idx >= total) return;
    int i = idx & 63;
    int t = idx >> 6;
    int h = t % nheads;
    int s = t / nheads;
    float sn = g_sin[s * 64 + i];
    float cs = g_cos[s * 64 + i];
    float* p = X + ((size_t)s * nheads + h) * HD;
    float x0 = p[i], x1 = p[i + 64];
    p[i]      = x0 * cs - x1 * sn;
    p[i + 64] = x1 * cs + x0 * sn;
}

// ---------------- HMMA GEMM: C = A @ B, fp16 3-term split, fp32 accum --------
// Tile 128x128, BK=32, 256 threads (8 warps, 2x4 warp grid, warp tile 64x32).
// A [M,K] smem [128][32] XOR-swizzled; B [K,N] smem [32][128] XOR-swizzled.
// ldmatrix.x4 (A) / ldmatrix.x4.trans (B); cp.async double-buffered.
// FUSED=1: QKV column-block select (28 Q | 4 K | 4 V).
template <int FUSED>
__global__ __launch_bounds__(256)
void gemm_hmma_kernel(const __half* __restrict__ Ahi, const __half* __restrict__ Alo,
                      const __half* __restrict__ Bhi0, const __half* __restrict__ Blo0,
                      const __half* __restrict__ Bhi1, const __half* __restrict__ Blo1,
                      const __half* __restrict__ Bhi2, const __half* __restrict__ Blo2,
                      float* __restrict__ C0, float* __restrict__ C1,
                      float* __restrict__ C2, int K, int N0) {
    extern __shared__ char smem[];
    uint32_t sb = smem_u32(smem);
    // stage layout: A_hi[0,8K) A_lo[8K,16K) B_hi[16K,24K) B_lo[24K,32K); x2 stages
    const uint32_t STG = 32768;

    int tid = threadIdx.x, wid = tid >> 5, lane = tid & 31;
    int bn = blockIdx.x, bm = blockIdx.y;
    int wm = wid & 1, wn = wid >> 1;

    const __half* Bhi = Bhi0;
    const __half* Blo = Blo0;
    float* C = C0;
    int ldn = N0, bcol = bn * 128;
    if (FUSED) {
        if (bn >= 28 && bn < 32) {
            Bhi = Bhi1; Blo = Blo1; C = C1; ldn = NKV * HD; bcol = (bn - 28) * 128;
        } else if (bn >= 32) {
            Bhi = Bhi2; Blo = Blo2; C = C2; ldn = NKV * HD; bcol = (bn - 32) * 128;
        }
    }

    // loader indices
    int ar0 = tid >> 2, ac0 = tid & 3;              // A: 512 chunks, 2/thread/array
    int ar1 = (tid + 256) >> 2, ac1 = tid & 3;
    int br0 = tid >> 4, bc0 = tid & 15;             // B: 512 chunks, 2/thread/array
    int br1 = (tid + 256) >> 4, bc1 = tid & 15;
    uint32_t a_d0 = (uint32_t)(ar0 * 64 + ((ac0 ^ ((ar0 >> 1) & 3)) << 4));
    uint32_t a_d1 = (uint32_t)(ar1 * 64 + ((ac1 ^ ((ar1 >> 1) & 3)) << 4));
    uint32_t b_d0 = (uint32_t)(br0 * 256 + ((bc0 ^ (br0 & 7)) << 4));
    uint32_t b_d1 = (uint32_t)(br1 * 256 + ((bc1 ^ (br1 & 7)) << 4));

    const int nch = K >> 5;

#define LOAD_STAGE(buf, ch) do {                                              \
    uint32_t base = sb + (uint32_t)(buf) * STG;                               \
    const __half* ah = Ahi + (size_t)(bm * 128) * K + (ch) * 32;              \
    const __half* al = Alo + (size_t)(bm * 128) * K + (ch) * 32;              \
    CPASYNC16(base + a_d0,          ah + (size_t)ar0 * K + ac0 * 8);          \
    CPASYNC16(base + a_d1,          ah + (size_t)ar1 * K + ac1 * 8);          \
    CPASYNC16(base + 8192 + a_d0,   al + (size_t)ar0 * K + ac0 * 8);          \
    CPASYNC16(base + 8192 + a_d1,   al + (size_t)ar1 * K + ac1 * 8);          \
    const __half* bh = Bhi + (size_t)((ch) * 32) * ldn + bcol;                \
    const __half* bl = Blo + (size_t)((ch) * 32) * ldn + bcol;                \
    CPASYNC16(base + 16384 + b_d0,  bh + (size_t)br0 * ldn + bc0 * 8);        \
    CPASYNC16(base + 16384 + b_d1,  bh + (size_t)br1 * ldn + bc1 * 8);        \
    CPASYNC16(base + 24576 + b_d0,  bl + (size_t)br0 * ldn + bc0 * 8);        \
    CPASYNC16(base + 24576 + b_d1,  bl + (size_t)br1 * ldn + bc1 * 8);        \
} while (0)

    // per-thread ldmatrix address components
    int mat = lane >> 3;
    int arb = wm * 64 + ((mat & 1) << 3) + (lane & 7);  // A row base
    int asw = (arb >> 1) & 3;                            // A swizzle key (mt-invariant)
    int bkb = ((mat & 1) << 3) + (lane & 7);             // B k-row base
    int bsw = lane & 7;                                  // B swizzle key
    int bnc = wn * 4 + (mat >> 1);                       // B n-chunk base

    float acc[4][4][4];
#pragma unroll
    for (int i = 0; i < 4; i++)
#pragma unroll
        for (int j = 0; j < 4; j++)
#pragma unroll
            for (int q = 0; q < 4; q++) acc[i][j][q] = 0.f;

    LOAD_STAGE(0, 0);
    CP_COMMIT();

    for (int ch = 0; ch < nch; ch++) {
        if (ch + 1 < nch) {
            LOAD_STAGE((ch + 1) & 1, ch + 1);
            CP_COMMIT();
            CP_WAIT1();
        } else {
            CP_WAIT0();
        }
        __syncthreads();

        uint32_t Ab_hi = sb + (uint32_t)(ch & 1) * STG;
        uint32_t Ab_lo = Ab_hi + 8192;
        uint32_t Bb_hi = Ab_hi + 16384;
        uint32_t Bb_lo = Ab_hi + 24576;

#pragma unroll
        for (int kh = 0; kh < 2; kh++) {
            uint32_t ac = (uint32_t)(((kh * 2 + (mat >> 1)) ^ asw) << 4);
            uint32_t a_hi[4][4], a_lo[4][4];
#pragma unroll
            for (int mt = 0; mt < 4; mt++) {
                uint32_t ro = (uint32_t)((arb + mt * 16) * 64);
                ldsm_x4(a_hi[mt], Ab_hi + ro + ac);
                ldsm_x4(a_lo[mt], Ab_lo + ro + ac);
            }
            uint32_t bro = (uint32_t)((kh * 16 + bkb) * 256);
            uint32_t b_hi[2][4], b_lo[2][4];
#pragma unroll
            for (int p = 0; p < 2; p++) {
                uint32_t co = (uint32_t)((((bnc + p * 2)) ^ bsw) << 4);
                ldsm_x4t(b_hi[p], Bb_hi + bro + co);
                ldsm_x4t(b_lo[p], Bb_lo + bro + co);
            }
#pragma unroll
            for (int mt = 0; mt < 4; mt++)
#pragma unroll
                for (int p = 0; p < 2; p++) {
                    mma16816(acc[mt][p * 2],     a_hi[mt], b_hi[p][0], b_hi[p][1]);
                    mma16816(acc[mt][p * 2 + 1], a_hi[mt], b_hi[p][2], b_hi[p][3]);
                    mma16816(acc[mt][p * 2],     a_hi[mt], b_lo[p][0], b_lo[p][1]);
                    mma16816(acc[mt][p * 2 + 1], a_hi[mt], b_lo[p][2], b_lo[p][3]);
                    mma16816(acc[mt][p * 2],     a_lo[mt], b_hi[p][0], b_hi[p][1]);
                    mma16816(acc[mt][p * 2 + 1], a_lo[mt], b_hi[p][2], b_hi[p][3]);
                }
        }
        __syncthreads();
    }
#undef LOAD_STAGE

    // epilogue: frag (mt, nt) -> rows wm*64+mt*16+(l>>2)(+8), cols wn*32+(nt>>1)*16+(nt&1)*8+(l&3)*2
#pragma unroll
    for (int mt = 0; mt < 4; mt++) {
        int row = bm * 128 + wm * 64 + mt * 16 + (lane >> 2);
#pragma unroll
        for (int nt = 0; nt < 4; nt++) {
            int col = bcol + wn * 32 + (nt >> 1) * 16 + (nt & 1) * 8 + (lane & 3) * 2;
            *(float2*)(C + (size_t)row * ldn + col) =
                make_float2(acc[mt][nt][0], acc[mt][nt][1]);
            *(float2*)(C + (size_t)(row + 8) * ldn + col) =
                make_float2(acc[mt][nt][2], acc[mt][nt][3]);
        }
    }
}

// ---------------- Flash attention (fp32 FFMA2, R3 design) -------------------
__global__ __launch_bounds__(256)
void flash_kernel(const float* __restrict__ Q, const float* __restrict__ K,
                  const float* __restrict__ V, const int* __restrict__ amask,
                  float* __restrict__ O) {
    extern __shared__ float sh[];
    float* Qs = sh;                     // 128 x 132
    float* Ks = Qs + 128 * 132;         // 64 x 132
    float* Vs = Ks + 64 * 132;          // 64 x 132
    ull*   Psd = (ull*)(Vs + 64 * 132); // 128 x 66 packed (p,p)

    int qb = (gridDim.x - 1) - blockIdx.x;  // heavy tiles first
    int h = blockIdx.y;
    int kvh = h / REP;
    int tid = threadIdx.x;
    int tm = tid >> 4, tn = tid & 15;
    int r0 = tm * 8, c0 = tn * 4, d0 = tn * 8;

    for (int i = tid; i < 128 * 32; i += 256) {
        int rr = i >> 5, c4 = (i & 31) * 4;
        *(float4*)&Qs[rr * 132 + c4] =
            *(const float4*)(Q + ((size_t)(qb * 128 + rr) * NH + h) * HD + c4);
    }

    float m[8], l[8];
    ull o2[8][4];
#pragma unroll
    for (int i = 0; i < 8; i++) {
        m[i] = -1e30f; l[i] = 0.f;
#pragma unroll
        for (int d = 0; d < 4; d++) o2[i][d] = 0ULL;
    }
    __syncthreads();

    const float scale = 0.0883883476483184406f;  // 1/sqrt(128)
    int kbmax = 2 * qb + 1;

    for (int kb = 0; kb <= kbmax; kb++) {
        for (int i = tid; i < 64 * 32; i += 256) {
            int rr = i >> 5, c4 = (i & 31) * 4;
            size_t off = ((size_t)(kb * 64 + rr) * NKV + kvh) * HD + c4;
            *(float4*)&Ks[rr * 132 + c4] = *(const float4*)(K + off);
            *(float4*)&Vs[rr * 132 + c4] = *(const float4*)(V + off);
        }
        __syncthreads();

        ull s2[8][4];
#pragma unroll
        for (int i = 0; i < 8; i++)
#pragma unroll
            for (int j = 0; j < 4; j++) s2[i][j] = 0ULL;

#pragma unroll 4
        for (int d4 = 0; d4 < 32; d4++) {
            ull kb0[4], kb1[4];
#pragma unroll
            for (int j = 0; j < 4; j++) {
                ulonglong2 t = *(const ulonglong2*)&Ks[(c0 + j) * 132 + d4 * 4];
                kb0[j] = t.x; kb1[j] = t.y;
            }
#pragma unroll
            for (int i = 0; i < 8; i++) {
                ulonglong2 qa = *(const ulonglong2*)&Qs[(r0 + i) * 132 + d4 * 4];
#pragma unroll
                for (int j = 0; j < 4; j++) {
                    ffma2(s2[i][j], qa.x, kb0[j]);
                    ffma2(s2[i][j], qa.y, kb1[j]);
                }
            }
        }

        int grow = qb * 128 + r0, gcol = kb * 64 + c0;
        int mk[4];
#pragma unroll
        for (int j = 0; j < 4; j++) mk[j] = __ldg(&amask[gcol + j]);

        float s[8][4];
#pragma unroll
        for (int i = 0; i < 8; i++)
#pragma unroll
            for (int j = 0; j < 4; j++) {
                float sv = (lo2(s2[i][j]) + hi2(s2[i][j])) * scale;
                if (gcol + j > grow + i || mk[j] == 0) sv = -1e30f;
                s[i][j] = sv;
            }

#pragma unroll
        for (int i = 0; i < 8; i++) {
            float rmax = fmaxf(fmaxf(s[i][0], s[i][1]), fmaxf(s[i][2], s[i][3]));
#pragma unroll
            for (int off = 1; off < 16; off <<= 1)
                rmax = fmaxf(rmax, __shfl_xor_sync(0xffffffffu, rmax, off));
            float mn = fmaxf(m[i], rmax);
            float alpha = __expf(m[i] - mn);
            m[i] = mn;
            float rs = 0.f;
#pragma unroll
            for (int j = 0; j < 4; j++) {
                float p = __expf(s[i][j] - mn);
                s[i][j] = p;
                rs += p;
            }
#pragma unroll
            for (int off = 1; off < 16; off <<= 1)
                rs += __shfl_xor_sync(0xffffffffu, rs, off);
            l[i] = l[i] * alpha + rs;
            ull ad = dup2(alpha);
#pragma unroll
            for (int d = 0; d < 4; d++) o2[i][d] = fmul2(o2[i][d], ad);
#pragma unroll
            for (int j = 0; j < 4; j++)
                Psd[(r0 + i) * 66 + c0 + j] = dup2(s[i][j]);
        }
        __syncthreads();

#pragma unroll 2
        for (int c = 0; c < 64; c++) {
            ulonglong2 v0 = *(const ulonglong2*)&Vs[c * 132 + d0];
            ulonglong2 v1 = *(const ulonglong2*)&Vs[c * 132 + d0 + 4];
#pragma unroll
            for (int i = 0; i < 8; i++) {
                ull pd = Psd[(r0 + i) * 66 + c];
                ffma2(o2[i][0], pd, v0.x);
                ffma2(o2[i][1], pd, v0.y);
                ffma2(o2[i][2], pd, v1.x);
                ffma2(o2[i][3], pd, v1.y);
            }
        }
        __syncthreads();
    }

#pragma unroll
    for (int i = 0; i < 8; i++) {
        float inv = 1.f / l[i];
        float* op = O + ((size_t)(qb * 128 + r0 + i) * NH + h) * HD + d0;
        *(float4*)(op)     = make_float4(lo2(o2[i][0]) * inv, hi2(o2[i][0]) * inv,
                                         lo2(o2[i][1]) * inv, hi2(o2[i][1]) * inv);
        *(float4*)(op + 4) = make_float4(lo2(o2[i][2]) * inv, hi2(o2[i][2]) * inv,
                                         lo2(o2[i][3]) * inv, hi2(o2[i][3]) * inv);
    }
}

// ---------------- launcher ---------------------------------------------------
extern "C" void kernel_launch(void* const* d_in, const int* in_sizes, int n_in,
                              void* d_out, int out_size) {
    const float* x     = (const float*)d_in[0];
    const int*   amask = (const int*)  d_in[1];
    const int*   pos   = (const int*)  d_in[2];
    const float* Wq    = (const float*)d_in[3];
    const float* Wk    = (const float*)d_in[4];
    const float* Wv    = (const float*)d_in[5];
    const float* Wo    = (const float*)d_in[6];
    float* out = (float*)d_out;

    float *qp, *kp, *vp, *ap;
    cudaGetSymbolAddress((void**)&qp, g_q);
    cudaGetSymbolAddress((void**)&kp, g_k);
    cudaGetSymbolAddress((void**)&vp, g_v);
    cudaGetSymbolAddress((void**)&ap, g_attn);
    __half *xh, *xl, *qh, *ql, *kh, *kl, *vh, *vl, *oh, *ol, *ah, *al;
    cudaGetSymbolAddress((void**)&xh, g_x_hi);  cudaGetSymbolAddress((void**)&xl, g_x_lo);
    cudaGetSymbolAddress((void**)&qh, g_wq_hi); cudaGetSymbolAddress((void**)&ql, g_wq_lo);
    cudaGetSymbolAddress((void**)&kh, g_wk_hi); cudaGetSymbolAddress((void**)&kl, g_wk_lo);
    cudaGetSymbolAddress((void**)&vh, g_wv_hi); cudaGetSymbolAddress((void**)&vl, g_wv_lo);
    cudaGetSymbolAddress((void**)&oh, g_wo_hi); cudaGetSymbolAddress((void**)&ol, g_wo_lo);
    cudaGetSymbolAddress((void**)&ah, g_a_hi);  cudaGetSymbolAddress((void**)&al, g_a_lo);

    // 0) splits
    split_kernel<<<(S_LEN * HID / 4 + 255) / 256, 256>>>(x, xh, xl, S_LEN * HID / 4);
    split_kernel<<<(HID * NH * HD / 4 + 255) / 256, 256>>>(Wq, qh, ql, HID * NH * HD / 4);
    split_kernel<<<(HID * NKV * HD / 4 + 255) / 256, 256>>>(Wk, kh, kl, HID * NKV * HD / 4);
    split_kernel<<<(HID * NKV * HD / 4 + 255) / 256, 256>>>(Wv, vh, vl, HID * NKV * HD / 4);
    split_kernel<<<(NH * HD * HID / 4 + 255) / 256, 256>>>(Wo, oh, ol, NH * HD * HID / 4);

    // 1) RoPE table
    build_rope_kernel<<<(S_LEN * 64 + 255) / 256, 256>>>(pos);

    // 2) fused QKV projection via HMMA
    const int gemm_smem = 65536;
    cudaFuncSetAttribute(gemm_hmma_kernel<1>,
                         cudaFuncAttributeMaxDynamicSharedMemorySize, gemm_smem);
    cudaFuncSetAttribute(gemm_hmma_kernel<0>,
                         cudaFuncAttributeMaxDynamicSharedMemorySize, gemm_smem);
    gemm_hmma_kernel<1><<<dim3(36, 16), 256, gemm_smem>>>(
        xh, xl, qh, ql, kh, kl, vh, vl, qp, kp, vp, HID, NH * HD);

    // 3) RoPE on Q and K
    rope_kernel<<<(S_LEN * NH * 64 + 255) / 256, 256>>>(qp, NH);
    rope_kernel<<<(S_LEN * NKV * 64 + 255) / 256, 256>>>(kp, NKV);

    // 4) flash attention
    size_t flash_smem = (size_t)(128 * 132 + 64 * 132 + 64 * 132) * sizeof(float)
                      + (size_t)(128 * 66) * sizeof(ull);
    cudaFuncSetAttribute(flash_kernel, cudaFuncAttributeMaxDynamicSharedMemorySize,
                         (int)flash_smem);
    flash_kernel<<<dim3(S_LEN / 128, NH), 256, flash_smem>>>(qp, kp, vp, amask, ap);

    // 5) split attn output, then O projection via HMMA
    split_kernel<<<(S_LEN * NH * HD / 4 + 255) / 256, 256>>>(ap, ah, al, S_LEN * NH * HD / 4);
    gemm_hmma_kernel<0><<<dim3(28, 16), 256, gemm_smem>>>(
        ah, al, oh, ol, nullptr, nullptr, nullptr, nullptr,
        out, nullptr, nullptr, HID, HID);
}

// round 6
// speedup vs baseline: 4.9726x; 1.8839x over previous
#include <cuda_runtime.h>
#include <cuda_fp16.h>
#include <math.h>
#include <cstdint>

#define S_LEN 2048
#define HID   3584
#define NH    28
#define NKV   4
#define HD    128
#define REP   7
#define NHD   (NH * HD)
#define QK_SCALE 0.0883883476483184406f

// ---------------- scratch (device globals; no allocations allowed) ----------
__device__ float g_q[S_LEN * NH * HD];
__device__ float g_k[S_LEN * NKV * HD];
__device__ float g_v[S_LEN * NKV * HD];
__device__ float g_sin[S_LEN * 64];
__device__ float g_cos[S_LEN * 64];

__device__ __align__(16) __half g_x_hi[S_LEN * HID];
__device__ __align__(16) __half g_x_lo[S_LEN * HID];
__device__ __align__(16) __half g_wq_hi[HID * NH * HD];
__device__ __align__(16) __half g_wq_lo[HID * NH * HD];
__device__ __align__(16) __half g_wk_hi[HID * NKV * HD];
__device__ __align__(16) __half g_wk_lo[HID * NKV * HD];
__device__ __align__(16) __half g_wv_hi[HID * NKV * HD];
__device__ __align__(16) __half g_wv_lo[HID * NKV * HD];
__device__ __align__(16) __half g_wo_hi[NH * HD * HID];
__device__ __align__(16) __half g_wo_lo[NH * HD * HID];
__device__ __align__(16) __half g_a_hi[S_LEN * NH * HD];
__device__ __align__(16) __half g_a_lo[S_LEN * NH * HD];
// flash operands
__device__ __align__(16) __half g_qhi[S_LEN * NH * HD];
__device__ __align__(16) __half g_qlo[S_LEN * NH * HD];
__device__ __align__(16) __half g_khiT[NKV * HD * S_LEN];   // [NKV][HD][S]
__device__ __align__(16) __half g_kloT[NKV * HD * S_LEN];
__device__ __align__(16) __half g_vhi[S_LEN * NKV * HD];
__device__ __align__(16) __half g_vlo[S_LEN * NKV * HD];

// ---------------- HMMA helpers (base-target instructions only) --------------
__device__ __forceinline__ uint32_t smem_u32(const void* p) {
    uint32_t a;
    asm("{ .reg .u64 t; cvta.to.shared.u64 t, %1; cvt.u32.u64 %0, t; }"
        : "=r"(a) : "l"(p));
    return a;
}
__device__ __forceinline__ void ldsm_x4(uint32_t* r, uint32_t addr) {
    asm volatile("ldmatrix.sync.aligned.m8n8.x4.shared.b16 {%0,%1,%2,%3}, [%4];"
        : "=r"(r[0]), "=r"(r[1]), "=r"(r[2]), "=r"(r[3]) : "r"(addr));
}
__device__ __forceinline__ void ldsm_x4t(uint32_t* r, uint32_t addr) {
    asm volatile("ldmatrix.sync.aligned.m8n8.x4.trans.shared.b16 {%0,%1,%2,%3}, [%4];"
        : "=r"(r[0]), "=r"(r[1]), "=r"(r[2]), "=r"(r[3]) : "r"(addr));
}
__device__ __forceinline__ void mma16816(float* d, const uint32_t* a,
                                         uint32_t b0, uint32_t b1) {
    asm volatile(
        "mma.sync.aligned.m16n8k16.row.col.f32.f16.f16.f32 "
        "{%0,%1,%2,%3}, {%4,%5,%6,%7}, {%8,%9}, {%0,%1,%2,%3};"
        : "+f"(d[0]), "+f"(d[1]), "+f"(d[2]), "+f"(d[3])
        : "r"(a[0]), "r"(a[1]), "r"(a[2]), "r"(a[3]), "r"(b0), "r"(b1));
}
#define CPASYNC16(dst, src) \
    asm volatile("cp.async.cg.shared.global [%0], [%1], 16;" \
                 :: "r"(dst), "l"(src) : "memory")
#define CP_COMMIT() asm volatile("cp.async.commit_group;" ::: "memory")
#define CP_WAIT1()  asm volatile("cp.async.wait_group 1;" ::: "memory")
#define CP_WAIT0()  asm volatile("cp.async.wait_group 0;" ::: "memory")

__device__ __forceinline__ void split2(float x, float y, uint32_t& hi, uint32_t& lo) {
    __half hx = __float2half_rn(x), hy = __float2half_rn(y);
    __half lx = __float2half_rn(x - __half2float(hx));
    __half ly = __float2half_rn(y - __half2float(hy));
    hi = (uint32_t)__half_as_ushort(hx) | ((uint32_t)__half_as_ushort(hy) << 16);
    lo = (uint32_t)__half_as_ushort(lx) | ((uint32_t)__half_as_ushort(ly) << 16);
}
__device__ __forceinline__ void store2(__half* hp, __half* lp, float x, float y) {
    uint32_t hb, lb;
    split2(x, y, hb, lb);
    *(uint32_t*)hp = hb;
    *(uint32_t*)lp = lb;
}

// ---------------- fp32 -> fp16 hi/lo split -----------------------------------
__global__ void split_kernel(const float* __restrict__ src,
                             __half* __restrict__ hi,
                             __half* __restrict__ lo, int n4) {
    int i = blockIdx.x * blockDim.x + threadIdx.x;
    if (i >= n4) return;
    float4 v = ((const float4*)src)[i];
    __half h0 = __float2half_rn(v.x), h1 = __float2half_rn(v.y);
    __half h2 = __float2half_rn(v.z), h3 = __float2half_rn(v.w);
    __half l0 = __float2half_rn(v.x - __half2float(h0));
    __half l1 = __float2half_rn(v.y - __half2float(h1));
    __half l2 = __float2half_rn(v.z - __half2float(h2));
    __half l3 = __float2half_rn(v.w - __half2float(h3));
    ((uint2*)hi)[i] = make_uint2(
        (uint32_t)__half_as_ushort(h0) | ((uint32_t)__half_as_ushort(h1) << 16),
        (uint32_t)__half_as_ushort(h2) | ((uint32_t)__half_as_ushort(h3) << 16));
    ((uint2*)lo)[i] = make_uint2(
        (uint32_t)__half_as_ushort(l0) | ((uint32_t)__half_as_ushort(l1) << 16),
        (uint32_t)__half_as_ushort(l2) | ((uint32_t)__half_as_ushort(l3) << 16));
}

// ---------------- RoPE sin/cos table -----------------------------------------
__global__ void build_rope_kernel(const int* __restrict__ pos) {
    int idx = blockIdx.x * blockDim.x + threadIdx.x;
    if (idx >= S_LEN * 64) return;
    int i = idx & 63;
    int s = idx >> 6;
    double inv = exp(-((double)i / 64.0) * log(1.0e6));
    double ang = (double)pos[s] * inv;
    g_sin[idx] = (float)sin(ang);
    g_cos[idx] = (float)cos(ang);
}

// ---------------- RoPE + split Q (scale folded in), layout [S,NH,HD] ---------
__global__ void rope_split_q_kernel(const float* __restrict__ X,
                                    __half* __restrict__ hi,
                                    __half* __restrict__ lo) {
    int idx = blockIdx.x * blockDim.x + threadIdx.x;
    if (idx >= S_LEN * NH * 64) return;
    int i = idx & 63;
    int t = idx >> 6;
    int h = t % NH;
    int s = t / NH;
    float sn = g_sin[s * 64 + i], cs = g_cos[s * 64 + i];
    const float* p = X + ((size_t)s * NH + h) * HD;
    float x0 = p[i], x1 = p[i + 64];
    float y0 = (x0 * cs - x1 * sn) * QK_SCALE;
    float y1 = (x1 * cs + x0 * sn) * QK_SCALE;
    size_t o = ((size_t)s * NH + h) * HD;
    __half h0 = __float2half_rn(y0);
    hi[o + i] = h0;
    lo[o + i] = __float2half_rn(y0 - __half2float(h0));
    __half h1 = __float2half_rn(y1);
    hi[o + i + 64] = h1;
    lo[o + i + 64] = __float2half_rn(y1 - __half2float(h1));
}

// ---------------- RoPE + split K, TRANSPOSED layout [NKV][HD][S] -------------
__global__ void rope_split_k_kernel(const float* __restrict__ X,
                                    __half* __restrict__ hiT,
                                    __half* __restrict__ loT) {
    int idx = blockIdx.x * blockDim.x + threadIdx.x;
    if (idx >= S_LEN * NKV * 64) return;
    int s = idx & (S_LEN - 1);
    int t = idx >> 11;
    int i = t & 63;
    int kvh = t >> 6;
    float sn = g_sin[s * 64 + i], cs = g_cos[s * 64 + i];
    const float* p = X + ((size_t)s * NKV + kvh) * HD;
    float x0 = p[i], x1 = p[i + 64];
    float y0 = x0 * cs - x1 * sn;
    float y1 = x1 * cs + x0 * sn;
    size_t o0 = ((size_t)kvh * HD + i) * S_LEN + s;
    size_t o1 = ((size_t)kvh * HD + i + 64) * S_LEN + s;
    __half h0 = __float2half_rn(y0);
    hiT[o0] = h0;
    loT[o0] = __float2half_rn(y0 - __half2float(h0));
    __half h1 = __float2half_rn(y1);
    hiT[o1] = h1;
    loT[o1] = __float2half_rn(y1 - __half2float(h1));
}

// ---------------- HMMA GEMM (verified in R5): C = A @ B, fp16 3-term --------
template <int FUSED>
__global__ __launch_bounds__(256)
void gemm_hmma_kernel(const __half* __restrict__ Ahi, const __half* __restrict__ Alo,
                      const __half* __restrict__ Bhi0, const __half* __restrict__ Blo0,
                      const __half* __restrict__ Bhi1, const __half* __restrict__ Blo1,
                      const __half* __restrict__ Bhi2, const __half* __restrict__ Blo2,
                      float* __restrict__ C0, float* __restrict__ C1,
                      float* __restrict__ C2, int K, int N0) {
    extern __shared__ char smem[];
    uint32_t sb = smem_u32(smem);
    const uint32_t STG = 32768;

    int tid = threadIdx.x, wid = tid >> 5, lane = tid & 31;
    int bn = blockIdx.x, bm = blockIdx.y;
    int wm = wid & 1, wn = wid >> 1;

    const __half* Bhi = Bhi0;
    const __half* Blo = Blo0;
    float* C = C0;
    int ldn = N0, bcol = bn * 128;
    if (FUSED) {
        if (bn >= 28 && bn < 32) {
            Bhi = Bhi1; Blo = Blo1; C = C1; ldn = NKV * HD; bcol = (bn - 28) * 128;
        } else if (bn >= 32) {
            Bhi = Bhi2; Blo = Blo2; C = C2; ldn = NKV * HD; bcol = (bn - 32) * 128;
        }
    }

    int ar0 = tid >> 2, ac0 = tid & 3;
    int ar1 = (tid + 256) >> 2, ac1 = tid & 3;
    int br0 = tid >> 4, bc0 = tid & 15;
    int br1 = (tid + 256) >> 4, bc1 = tid & 15;
    uint32_t a_d0 = (uint32_t)(ar0 * 64 + ((ac0 ^ ((ar0 >> 1) & 3)) << 4));
    uint32_t a_d1 = (uint32_t)(ar1 * 64 + ((ac1 ^ ((ar1 >> 1) & 3)) << 4));
    uint32_t b_d0 = (uint32_t)(br0 * 256 + ((bc0 ^ (br0 & 7)) << 4));
    uint32_t b_d1 = (uint32_t)(br1 * 256 + ((bc1 ^ (br1 & 7)) << 4));

    const int nch = K >> 5;

#define LOAD_STAGE(buf, ch) do {                                              \
    uint32_t base = sb + (uint32_t)(buf) * STG;                               \
    const __half* ah = Ahi + (size_t)(bm * 128) * K + (ch) * 32;              \
    const __half* al = Alo + (size_t)(bm * 128) * K + (ch) * 32;              \
    CPASYNC16(base + a_d0,          ah + (size_t)ar0 * K + ac0 * 8);          \
    CPASYNC16(base + a_d1,          ah + (size_t)ar1 * K + ac1 * 8);          \
    CPASYNC16(base + 8192 + a_d0,   al + (size_t)ar0 * K + ac0 * 8);          \
    CPASYNC16(base + 8192 + a_d1,   al + (size_t)ar1 * K + ac1 * 8);          \
    const __half* bh = Bhi + (size_t)((ch) * 32) * ldn + bcol;                \
    const __half* bl = Blo + (size_t)((ch) * 32) * ldn + bcol;                \
    CPASYNC16(base + 16384 + b_d0,  bh + (size_t)br0 * ldn + bc0 * 8);        \
    CPASYNC16(base + 16384 + b_d1,  bh + (size_t)br1 * ldn + bc1 * 8);        \
    CPASYNC16(base + 24576 + b_d0,  bl + (size_t)br0 * ldn + bc0 * 8);        \
    CPASYNC16(base + 24576 + b_d1,  bl + (size_t)br1 * ldn + bc1 * 8);        \
} while (0)

    int mat = lane >> 3;
    int arb = wm * 64 + ((mat & 1) << 3) + (lane & 7);
    int asw = (arb >> 1) & 3;
    int bkb = ((mat & 1) << 3) + (lane & 7);
    int bsw = lane & 7;
    int bnc = wn * 4 + (mat >> 1);

    float acc[4][4][4];
#pragma unroll
    for (int i = 0; i < 4; i++)
#pragma unroll
        for (int j = 0; j < 4; j++)
#pragma unroll
            for (int q = 0; q < 4; q++) acc[i][j][q] = 0.f;

    LOAD_STAGE(0, 0);
    CP_COMMIT();

    for (int ch = 0; ch < nch; ch++) {
        if (ch + 1 < nch) {
            LOAD_STAGE((ch + 1) & 1, ch + 1);
            CP_COMMIT();
            CP_WAIT1();
        } else {
            CP_WAIT0();
        }
        __syncthreads();

        uint32_t Ab_hi = sb + (uint32_t)(ch & 1) * STG;
        uint32_t Ab_lo = Ab_hi + 8192;
        uint32_t Bb_hi = Ab_hi + 16384;
        uint32_t Bb_lo = Ab_hi + 24576;

#pragma unroll
        for (int kh = 0; kh < 2; kh++) {
            uint32_t ac = (uint32_t)(((kh * 2 + (mat >> 1)) ^ asw) << 4);
            uint32_t a_hi[4][4], a_lo[4][4];
#pragma unroll
            for (int mt = 0; mt < 4; mt++) {
                uint32_t ro = (uint32_t)((arb + mt * 16) * 64);
                ldsm_x4(a_hi[mt], Ab_hi + ro + ac);
                ldsm_x4(a_lo[mt], Ab_lo + ro + ac);
            }
            uint32_t bro = (uint32_t)((kh * 16 + bkb) * 256);
            uint32_t b_hi[2][4], b_lo[2][4];
#pragma unroll
            for (int p = 0; p < 2; p++) {
                uint32_t co = (uint32_t)((((bnc + p * 2)) ^ bsw) << 4);
                ldsm_x4t(b_hi[p], Bb_hi + bro + co);
                ldsm_x4t(b_lo[p], Bb_lo + bro + co);
            }
#pragma unroll
            for (int mt = 0; mt < 4; mt++)
#pragma unroll
                for (int p = 0; p < 2; p++) {
                    mma16816(acc[mt][p * 2],     a_hi[mt], b_hi[p][0], b_hi[p][1]);
                    mma16816(acc[mt][p * 2 + 1], a_hi[mt], b_hi[p][2], b_hi[p][3]);
                    mma16816(acc[mt][p * 2],     a_hi[mt], b_lo[p][0], b_lo[p][1]);
                    mma16816(acc[mt][p * 2 + 1], a_hi[mt], b_lo[p][2], b_lo[p][3]);
                    mma16816(acc[mt][p * 2],     a_lo[mt], b_hi[p][0], b_hi[p][1]);
                    mma16816(acc[mt][p * 2 + 1], a_lo[mt], b_hi[p][2], b_hi[p][3]);
                }
        }
        __syncthreads();
    }
#undef LOAD_STAGE

#pragma unroll
    for (int mt = 0; mt < 4; mt++) {
        int row = bm * 128 + wm * 64 + mt * 16 + (lane >> 2);
#pragma unroll
        for (int nt = 0; nt < 4; nt++) {
            int col = bcol + wn * 32 + (nt >> 1) * 16 + (nt & 1) * 8 + (lane & 3) * 2;
            *(float2*)(C + (size_t)row * ldn + col) =
                make_float2(acc[mt][nt][0], acc[mt][nt][1]);
            *(float2*)(C + (size_t)(row + 8) * ldn + col) =
                make_float2(acc[mt][nt][2], acc[mt][nt][3]);
        }
    }
}

// ---------------- HMMA flash attention: 3-term QK and PV --------------------
// CTA = (q-tile 128, head). 8 warps x 16 q-rows. k-tile 64, double-buffered.
// Q resident in smem (hi/lo). K transposed [d][s] tiles; V [s][d] tiles.
// P converted in-registers (C-frag -> A-frag repack). Output written as
// fp16 hi/lo directly for the O-projection.
__global__ __launch_bounds__(256, 1)
void flash_hmma_kernel(const __half* __restrict__ Qhi, const __half* __restrict__ Qlo,
                       const __half* __restrict__ KhiT, const __half* __restrict__ KloT,
                       const __half* __restrict__ Vhi, const __half* __restrict__ Vlo,
                       const int* __restrict__ amask,
                       __half* __restrict__ Ahi, __half* __restrict__ Alo) {
    extern __shared__ char sm[];
    uint32_t sb = smem_u32(sm);
    float* sbias = (float*)(sm + 196608);

    int tid = threadIdx.x, wq = tid >> 5, lane = tid & 31;
    int mat = lane >> 3, l7 = lane & 7, qd = lane >> 2, l3 = lane & 3;
    int qb = (int)(gridDim.x - 1 - blockIdx.x);   // heavy tiles first
    int h = blockIdx.y, kvh = h / REP;

    // Q tile: 128 rows x 256B, hi at 0, lo at 32768
    {
        const __half* qh = Qhi + ((size_t)(qb * 128) * NH + h) * HD;
        const __half* ql = Qlo + ((size_t)(qb * 128) * NH + h) * HD;
#pragma unroll
        for (int i = 0; i < 8; i++) {
            int idx = tid + i * 256;
            int row = idx >> 4, ch = idx & 15;
            uint32_t dst = sb + (uint32_t)(row * 256 + ((ch ^ (row & 7)) << 4));
            CPASYNC16(dst,         qh + (size_t)row * NHD + ch * 8);
            CPASYNC16(dst + 32768, ql + (size_t)row * NHD + ch * 8);
        }
    }

    // K/V stage loader. stage base 65536 + s*65536:
    //   Khi [128 d][128B] at +0, Klo at +16384, Vhi [64 s][256B] at +32768, Vlo +49152
    auto load_kv = [&](int stage, int kb) {
        uint32_t base = sb + 65536u + (uint32_t)stage * 65536u;
        const __half* kh_ = KhiT + (size_t)kvh * HD * S_LEN + kb * 64;
        const __half* kl_ = KloT + (size_t)kvh * HD * S_LEN + kb * 64;
#pragma unroll
        for (int i = 0; i < 4; i++) {
            int idx = tid + i * 256;
            int row = idx >> 3, ch = idx & 7;
            uint32_t dst = base + (uint32_t)(row * 128 + ((ch ^ (row & 7)) << 4));
            CPASYNC16(dst,         kh_ + (size_t)row * S_LEN + ch * 8);
            CPASYNC16(dst + 16384, kl_ + (size_t)row * S_LEN + ch * 8);
        }
        const __half* vh_ = Vhi + ((size_t)(kb * 64) * NKV + kvh) * HD;
        const __half* vl_ = Vlo + ((size_t)(kb * 64) * NKV + kvh) * HD;
#pragma unroll
        for (int i = 0; i < 4; i++) {
            int idx = tid + i * 256;
            int row = idx >> 4, ch = idx & 15;
            uint32_t dst = base + 32768u + (uint32_t)(row * 256 + ((ch ^ (row & 7)) << 4));
            CPASYNC16(dst,         vh_ + (size_t)row * NKV * HD + ch * 8);
            CPASYNC16(dst + 16384, vl_ + (size_t)row * NKV * HD + ch * 8);
        }
    };

    load_kv(0, 0);
    CP_COMMIT();

    float o[16][4];
#pragma unroll
    for (int i = 0; i < 16; i++)
#pragma unroll
        for (int j = 0; j < 4; j++) o[i][j] = 0.f;
    float m0 = -1e30f, m1 = -1e30f, l0 = 0.f, l1 = 0.f;

    int kbmax = 2 * qb + 1;
    int r0g = qb * 128 + wq * 16 + qd, r1g = r0g + 8;
    int arow = wq * 16 + ((mat & 1) << 3) + l7;
    int brow0 = ((mat & 1) << 3) + l7;

    for (int kb = 0; kb <= kbmax; kb++) {
        if (kb < kbmax) {
            load_kv((kb + 1) & 1, kb + 1);
            CP_COMMIT();
            CP_WAIT1();
        } else {
            CP_WAIT0();
        }
        if (tid < 64) sbias[tid] = amask[kb * 64 + tid] ? 0.f : -1e30f;
        __syncthreads();

        uint32_t Kb = sb + 65536u + (uint32_t)(kb & 1) * 65536u;
        uint32_t Vb = Kb + 32768u;

        // ---- S = Q K^T (3-term), 16x64 per warp
        float s[8][4];
#pragma unroll
        for (int i = 0; i < 8; i++)
#pragma unroll
            for (int j = 0; j < 4; j++) s[i][j] = 0.f;

#pragma unroll
        for (int kh2 = 0; kh2 < 8; kh2++) {
            uint32_t a_hi[4], a_lo[4];
            int ach = kh2 * 2 + (mat >> 1);
            uint32_t aaddr = sb + (uint32_t)(arow * 256 + ((ach ^ (arow & 7)) << 4));
            ldsm_x4(a_hi, aaddr);
            ldsm_x4(a_lo, aaddr + 32768);
            int brow = kh2 * 16 + brow0;
#pragma unroll
            for (int hf = 0; hf < 2; hf++) {
                uint32_t b_hi[2][4], b_lo[2][4];
#pragma unroll
                for (int p = 0; p < 2; p++) {
                    int bch = (hf * 2 + p) * 2 + (mat >> 1);
                    uint32_t baddr = Kb + (uint32_t)(brow * 128 + ((bch ^ (brow & 7)) << 4));
                    ldsm_x4t(b_hi[p], baddr);
                    ldsm_x4t(b_lo[p], baddr + 16384);
                }
#pragma unroll
                for (int p = 0; p < 2; p++)
#pragma unroll
                    for (int e = 0; e < 2; e++) {
                        int nt = hf * 4 + p * 2 + e;
                        mma16816(s[nt], a_hi, b_hi[p][e * 2], b_hi[p][e * 2 + 1]);
                        mma16816(s[nt], a_hi, b_lo[p][e * 2], b_lo[p][e * 2 + 1]);
                        mma16816(s[nt], a_lo, b_hi[p][e * 2], b_hi[p][e * 2 + 1]);
                    }
            }
        }

        // ---- padding + causal mask
#pragma unroll
        for (int nt = 0; nt < 8; nt++) {
            int c = nt * 8 + 2 * l3;
            float b0 = sbias[c], b1 = sbias[c + 1];
            s[nt][0] += b0; s[nt][1] += b1; s[nt][2] += b0; s[nt][3] += b1;
        }
        if (kb >= 2 * qb) {
            int cbase = kb * 64 + 2 * l3;
#pragma unroll
            for (int nt = 0; nt < 8; nt++) {
                int c0 = cbase + nt * 8, c1 = c0 + 1;
                if (c0 > r0g) s[nt][0] = -1e30f;
                if (c1 > r0g) s[nt][1] = -1e30f;
                if (c0 > r1g) s[nt][2] = -1e30f;
                if (c1 > r1g) s[nt][3] = -1e30f;
            }
        }

        // ---- online softmax (rows r0g, r1g; quad reduction)
        float mx0 = -1e30f, mx1 = -1e30f;
#pragma unroll
        for (int nt = 0; nt < 8; nt++) {
            mx0 = fmaxf(mx0, fmaxf(s[nt][0], s[nt][1]));
            mx1 = fmaxf(mx1, fmaxf(s[nt][2], s[nt][3]));
        }
        mx0 = fmaxf(mx0, __shfl_xor_sync(0xffffffffu, mx0, 1));
        mx0 = fmaxf(mx0, __shfl_xor_sync(0xffffffffu, mx0, 2));
        mx1 = fmaxf(mx1, __shfl_xor_sync(0xffffffffu, mx1, 1));
        mx1 = fmaxf(mx1, __shfl_xor_sync(0xffffffffu, mx1, 2));
        float mn0 = fmaxf(m0, mx0), mn1 = fmaxf(m1, mx1);
        float al0 = __expf(m0 - mn0), al1 = __expf(m1 - mn1);
        m0 = mn0; m1 = mn1;
        float rs0 = 0.f, rs1 = 0.f;
#pragma unroll
        for (int nt = 0; nt < 8; nt++) {
            s[nt][0] = __expf(s[nt][0] - mn0); rs0 += s[nt][0];
            s[nt][1] = __expf(s[nt][1] - mn0); rs0 += s[nt][1];
            s[nt][2] = __expf(s[nt][2] - mn1); rs1 += s[nt][2];
            s[nt][3] = __expf(s[nt][3] - mn1); rs1 += s[nt][3];
        }
        rs0 += __shfl_xor_sync(0xffffffffu, rs0, 1);
        rs0 += __shfl_xor_sync(0xffffffffu, rs0, 2);
        rs1 += __shfl_xor_sync(0xffffffffu, rs1, 1);
        rs1 += __shfl_xor_sync(0xffffffffu, rs1, 2);
        l0 = l0 * al0 + rs0;
        l1 = l1 * al1 + rs1;
#pragma unroll
        for (int nt = 0; nt < 16; nt++) {
            o[nt][0] *= al0; o[nt][1] *= al0;
            o[nt][2] *= al1; o[nt][3] *= al1;
        }

        // ---- O += P V (3-term). P repacked in-registers to A-frags.
#pragma unroll
        for (int j = 0; j < 4; j++) {
            uint32_t phi[4], plo[4];
            split2(s[2 * j][0],     s[2 * j][1],     phi[0], plo[0]);
            split2(s[2 * j][2],     s[2 * j][3],     phi[1], plo[1]);
            split2(s[2 * j + 1][0], s[2 * j + 1][1], phi[2], plo[2]);
            split2(s[2 * j + 1][2], s[2 * j + 1][3], phi[3], plo[3]);
            int vrow = j * 16 + ((mat & 1) << 3) + l7;
#pragma unroll
            for (int nb = 0; nb < 8; nb++) {
                uint32_t v_hi[4], v_lo[4];
                int vch = nb * 2 + (mat >> 1);
                uint32_t vaddr = Vb + (uint32_t)(vrow * 256 + ((vch ^ (vrow & 7)) << 4));
                ldsm_x4t(v_hi, vaddr);
                ldsm_x4t(v_lo, vaddr + 16384);
#pragma unroll
                for (int e = 0; e < 2; e++) {
                    int nt = nb * 2 + e;
                    mma16816(o[nt], phi, v_hi[e * 2], v_hi[e * 2 + 1]);
                    mma16816(o[nt], phi, v_lo[e * 2], v_lo[e * 2 + 1]);
                    mma16816(o[nt], plo, v_hi[e * 2], v_hi[e * 2 + 1]);
                }
            }
        }
        __syncthreads();
    }

    // ---- normalize + store as fp16 hi/lo, layout [S, NH*HD]
    float inv0 = 1.f / l0, inv1 = 1.f / l1;
    size_t ro0 = (size_t)r0g * NHD + h * HD + 2 * l3;
    size_t ro1 = (size_t)r1g * NHD + h * HD + 2 * l3;
#pragma unroll
    for (int nt = 0; nt < 16; nt++) {
        store2(Ahi + ro0 + nt * 8, Alo + ro0 + nt * 8, o[nt][0] * inv0, o[nt][1] * inv0);
        store2(Ahi + ro1 + nt * 8, Alo + ro1 + nt * 8, o[nt][2] * inv1, o[nt][3] * inv1);
    }
}

// ---------------- launcher ---------------------------------------------------
extern "C" void kernel_launch(void* const* d_in, const int* in_sizes, int n_in,
                              void* d_out, int out_size) {
    const float* x     = (const float*)d_in[0];
    const int*   amask = (const int*)  d_in[1];
    const int*   pos   = (const int*)  d_in[2];
    const float* Wq    = (const float*)d_in[3];
    const float* Wk    = (const float*)d_in[4];
    const float* Wv    = (const float*)d_in[5];
    const float* Wo    = (const float*)d_in[6];
    float* out = (float*)d_out;

    float *qp, *kp, *vp;
    cudaGetSymbolAddress((void**)&qp, g_q);
    cudaGetSymbolAddress((void**)&kp, g_k);
    cudaGetSymbolAddress((void**)&vp, g_v);
    __half *xh, *xl, *wqh, *wql, *wkh, *wkl, *wvh, *wvl, *woh, *wol, *ah, *al;
    __half *qhi, *qlo, *khiT, *kloT, *vhi, *vlo;
    cudaGetSymbolAddress((void**)&xh,  g_x_hi);  cudaGetSymbolAddress((void**)&xl,  g_x_lo);
    cudaGetSymbolAddress((void**)&wqh, g_wq_hi); cudaGetSymbolAddress((void**)&wql, g_wq_lo);
    cudaGetSymbolAddress((void**)&wkh, g_wk_hi); cudaGetSymbolAddress((void**)&wkl, g_wk_lo);
    cudaGetSymbolAddress((void**)&wvh, g_wv_hi); cudaGetSymbolAddress((void**)&wvl, g_wv_lo);
    cudaGetSymbolAddress((void**)&woh, g_wo_hi); cudaGetSymbolAddress((void**)&wol, g_wo_lo);
    cudaGetSymbolAddress((void**)&ah,  g_a_hi);  cudaGetSymbolAddress((void**)&al,  g_a_lo);
    cudaGetSymbolAddress((void**)&qhi, g_qhi);   cudaGetSymbolAddress((void**)&qlo, g_qlo);
    cudaGetSymbolAddress((void**)&khiT, g_khiT); cudaGetSymbolAddress((void**)&kloT, g_kloT);
    cudaGetSymbolAddress((void**)&vhi, g_vhi);   cudaGetSymbolAddress((void**)&vlo, g_vlo);

    // 0) splits of inputs/weights
    split_kernel<<<(S_LEN * HID / 4 + 255) / 256, 256>>>(x, xh, xl, S_LEN * HID / 4);
    split_kernel<<<(HID * NH * HD / 4 + 255) / 256, 256>>>(Wq, wqh, wql, HID * NH * HD / 4);
    split_kernel<<<(HID * NKV * HD / 4 + 255) / 256, 256>>>(Wk, wkh, wkl, HID * NKV * HD / 4);
    split_kernel<<<(HID * NKV * HD / 4 + 255) / 256, 256>>>(Wv, wvh, wvl, HID * NKV * HD / 4);
    split_kernel<<<(NH * HD * HID / 4 + 255) / 256, 256>>>(Wo, woh, wol, NH * HD * HID / 4);

    // 1) RoPE table
    build_rope_kernel<<<(S_LEN * 64 + 255) / 256, 256>>>(pos);

    // 2) fused QKV projection (HMMA)
    const int gemm_smem = 65536;
    cudaFuncSetAttribute(gemm_hmma_kernel<1>,
                         cudaFuncAttributeMaxDynamicSharedMemorySize, gemm_smem);
    cudaFuncSetAttribute(gemm_hmma_kernel<0>,
                         cudaFuncAttributeMaxDynamicSharedMemorySize, gemm_smem);
    gemm_hmma_kernel<1><<<dim3(36, 16), 256, gemm_smem>>>(
        xh, xl, wqh, wql, wkh, wkl, wvh, wvl, qp, kp, vp, HID, NH * HD);

    // 3) RoPE + fp16 hi/lo split (Q: scale folded, K: transposed), V split
    rope_split_q_kernel<<<(S_LEN * NH * 64 + 255) / 256, 256>>>(qp, qhi, qlo);
    rope_split_k_kernel<<<(S_LEN * NKV * 64 + 255) / 256, 256>>>(kp, khiT, kloT);
    split_kernel<<<(S_LEN * NKV * HD / 4 + 255) / 256, 256>>>(vp, vhi, vlo,
                                                              S_LEN * NKV * HD / 4);

    // 4) HMMA flash attention -> writes attn output as fp16 hi/lo
    const int flash_smem = 196864;
    cudaFuncSetAttribute(flash_hmma_kernel,
                         cudaFuncAttributeMaxDynamicSharedMemorySize, flash_smem);
    flash_hmma_kernel<<<dim3(S_LEN / 128, NH), 256, flash_smem>>>(
        qhi, qlo, khiT, kloT, vhi, vlo, amask, ah, al);

    // 5) O projection (HMMA) -> final output
    gemm_hmma_kernel<0><<<dim3(28, 16), 256, gemm_smem>>>(
        ah, al, woh, wol, nullptr, nullptr, nullptr, nullptr,
        out, nullptr, nullptr, HID, HID);
}

// round 7
// speedup vs baseline: 5.4257x; 1.0911x over previous
#include <cuda_runtime.h>
#include <cuda_fp16.h>
#include <math.h>
#include <cstdint>

#define S_LEN 2048
#define HID   3584
#define NH    28
#define NKV   4
#define HD    128
#define REP   7
#define NHD   (NH * HD)
#define QK_SCALE 0.0883883476483184406f

// ---------------- scratch (device globals; no allocations allowed) ----------
__device__ float g_q[S_LEN * NH * HD];
__device__ float g_k[S_LEN * NKV * HD];
__device__ float g_v[S_LEN * NKV * HD];
__device__ float g_sin[S_LEN * 64];
__device__ float g_cos[S_LEN * 64];

__device__ __align__(16) __half g_x_hi[S_LEN * HID];
__device__ __align__(16) __half g_x_lo[S_LEN * HID];
__device__ __align__(16) __half g_wq_hi[HID * NH * HD];
__device__ __align__(16) __half g_wq_lo[HID * NH * HD];
__device__ __align__(16) __half g_wk_hi[HID * NKV * HD];
__device__ __align__(16) __half g_wk_lo[HID * NKV * HD];
__device__ __align__(16) __half g_wv_hi[HID * NKV * HD];
__device__ __align__(16) __half g_wv_lo[HID * NKV * HD];
__device__ __align__(16) __half g_wo_hi[NH * HD * HID];
__device__ __align__(16) __half g_wo_lo[NH * HD * HID];
__device__ __align__(16) __half g_a_hi[S_LEN * NH * HD];
// flash operands
__device__ __align__(16) __half g_qhi[S_LEN * NH * HD];
__device__ __align__(16) __half g_qlo[S_LEN * NH * HD];
__device__ __align__(16) __half g_khiT[NKV * HD * S_LEN];   // [NKV][HD][S]
__device__ __align__(16) __half g_kloT[NKV * HD * S_LEN];
__device__ __align__(16) __half g_vhi[S_LEN * NKV * HD];
__device__ __align__(16) __half g_vlo[S_LEN * NKV * HD];

// ---------------- HMMA helpers (base-target instructions only) --------------
__device__ __forceinline__ uint32_t smem_u32(const void* p) {
    uint32_t a;
    asm("{ .reg .u64 t; cvta.to.shared.u64 t, %1; cvt.u32.u64 %0, t; }"
        : "=r"(a) : "l"(p));
    return a;
}
__device__ __forceinline__ void ldsm_x4(uint32_t* r, uint32_t addr) {
    asm volatile("ldmatrix.sync.aligned.m8n8.x4.shared.b16 {%0,%1,%2,%3}, [%4];"
        : "=r"(r[0]), "=r"(r[1]), "=r"(r[2]), "=r"(r[3]) : "r"(addr));
}
__device__ __forceinline__ void ldsm_x4t(uint32_t* r, uint32_t addr) {
    asm volatile("ldmatrix.sync.aligned.m8n8.x4.trans.shared.b16 {%0,%1,%2,%3}, [%4];"
        : "=r"(r[0]), "=r"(r[1]), "=r"(r[2]), "=r"(r[3]) : "r"(addr));
}
__device__ __forceinline__ void mma16816(float* d, const uint32_t* a,
                                         uint32_t b0, uint32_t b1) {
    asm volatile(
        "mma.sync.aligned.m16n8k16.row.col.f32.f16.f16.f32 "
        "{%0,%1,%2,%3}, {%4,%5,%6,%7}, {%8,%9}, {%0,%1,%2,%3};"
        : "+f"(d[0]), "+f"(d[1]), "+f"(d[2]), "+f"(d[3])
        : "r"(a[0]), "r"(a[1]), "r"(a[2]), "r"(a[3]), "r"(b0), "r"(b1));
}
#define CPASYNC16(dst, src) \
    asm volatile("cp.async.cg.shared.global [%0], [%1], 16;" \
                 :: "r"(dst), "l"(src) : "memory")
#define CP_COMMIT() asm volatile("cp.async.commit_group;" ::: "memory")
#define CP_WAIT1()  asm volatile("cp.async.wait_group 1;" ::: "memory")
#define CP_WAIT0()  asm volatile("cp.async.wait_group 0;" ::: "memory")

__device__ __forceinline__ void split2(float x, float y, uint32_t& hi, uint32_t& lo) {
    __half hx = __float2half_rn(x), hy = __float2half_rn(y);
    __half lx = __float2half_rn(x - __half2float(hx));
    __half ly = __float2half_rn(y - __half2float(hy));
    hi = (uint32_t)__half_as_ushort(hx) | ((uint32_t)__half_as_ushort(hy) << 16);
    lo = (uint32_t)__half_as_ushort(lx) | ((uint32_t)__half_as_ushort(ly) << 16);
}

__device__ __forceinline__ void split4_at(const float* __restrict__ src,
                                          __half* __restrict__ hi,
                                          __half* __restrict__ lo, int i) {
    float4 v = ((const float4*)src)[i];
    __half h0 = __float2half_rn(v.x), h1 = __float2half_rn(v.y);
    __half h2 = __float2half_rn(v.z), h3 = __float2half_rn(v.w);
    __half l0 = __float2half_rn(v.x - __half2float(h0));
    __half l1 = __float2half_rn(v.y - __half2float(h1));
    __half l2 = __float2half_rn(v.z - __half2float(h2));
    __half l3 = __float2half_rn(v.w - __half2float(h3));
    ((uint2*)hi)[i] = make_uint2(
        (uint32_t)__half_as_ushort(h0) | ((uint32_t)__half_as_ushort(h1) << 16),
        (uint32_t)__half_as_ushort(h2) | ((uint32_t)__half_as_ushort(h3) << 16));
    ((uint2*)lo)[i] = make_uint2(
        (uint32_t)__half_as_ushort(l0) | ((uint32_t)__half_as_ushort(l1) << 16),
        (uint32_t)__half_as_ushort(l2) | ((uint32_t)__half_as_ushort(l3) << 16));
}

// ---------------- fused split of x + all four weights ------------------------
__global__ void split_all_kernel(const float* __restrict__ x,
                                 const float* __restrict__ wq,
                                 const float* __restrict__ wk,
                                 const float* __restrict__ wv,
                                 const float* __restrict__ wo,
                                 __half* xh, __half* xl, __half* qh, __half* ql,
                                 __half* kh, __half* kl, __half* vh, __half* vl,
                                 __half* oh, __half* ol) {
    const int C0 = S_LEN * HID / 4;              // 1835008
    const int C1 = C0 + HID * NH * HD / 4;       // 5046272
    const int C2 = C1 + HID * NKV * HD / 4;      // 5505024
    const int C3 = C2 + HID * NKV * HD / 4;      // 5963776
    const int C4 = C3 + NH * HD * HID / 4;       // 9175040
    int i = blockIdx.x * blockDim.x + threadIdx.x;
    if (i >= C4) return;
    if (i < C0)      split4_at(x,  xh, xl, i);
    else if (i < C1) split4_at(wq, qh, ql, i - C0);
    else if (i < C2) split4_at(wk, kh, kl, i - C1);
    else if (i < C3) split4_at(wv, vh, vl, i - C2);
    else             split4_at(wo, oh, ol, i - C3);
}

// ---------------- RoPE sin/cos table -----------------------------------------
__global__ void build_rope_kernel(const int* __restrict__ pos) {
    int idx = blockIdx.x * blockDim.x + threadIdx.x;
    if (idx >= S_LEN * 64) return;
    int i = idx & 63;
    int s = idx >> 6;
    double inv = exp(-((double)i / 64.0) * log(1.0e6));
    double ang = (double)pos[s] * inv;
    g_sin[idx] = (float)sin(ang);
    g_cos[idx] = (float)cos(ang);
}

// ---------------- fused: RoPE+split Q | RoPE+split K^T | split V -------------
__global__ void prep_attention_kernel(const float* __restrict__ Q,
                                      const float* __restrict__ Kc,
                                      const float* __restrict__ V,
                                      __half* __restrict__ qhi, __half* __restrict__ qlo,
                                      __half* __restrict__ khiT, __half* __restrict__ kloT,
                                      __half* __restrict__ vhi, __half* __restrict__ vlo) {
    const int R0 = S_LEN * NH * 64;              // 3670016
    const int R1 = R0 + S_LEN * NKV * 64;        // 4194304
    const int R2 = R1 + S_LEN * NKV * HD / 4;    // 4456448
    int idx = blockIdx.x * blockDim.x + threadIdx.x;
    if (idx >= R2) return;

    if (idx < R0) {
        // Q: rope + scale + split, layout [S, NH, HD]
        int i = idx & 63;
        int t = idx >> 6;
        int h = t % NH;
        int s = t / NH;
        float sn = g_sin[s * 64 + i], cs = g_cos[s * 64 + i];
        const float* p = Q + ((size_t)s * NH + h) * HD;
        float x0 = p[i], x1 = p[i + 64];
        float y0 = (x0 * cs - x1 * sn) * QK_SCALE;
        float y1 = (x1 * cs + x0 * sn) * QK_SCALE;
        size_t o = ((size_t)s * NH + h) * HD;
        __half h0 = __float2half_rn(y0);
        qhi[o + i] = h0;
        qlo[o + i] = __float2half_rn(y0 - __half2float(h0));
        __half h1 = __float2half_rn(y1);
        qhi[o + i + 64] = h1;
        qlo[o + i + 64] = __float2half_rn(y1 - __half2float(h1));
    } else if (idx < R1) {
        // K: rope + split, TRANSPOSED layout [NKV][HD][S]
        int j = idx - R0;
        int s = j & (S_LEN - 1);
        int t = j >> 11;
        int i = t & 63;
        int kvh = t >> 6;
        float sn = g_sin[s * 64 + i], cs = g_cos[s * 64 + i];
        const float* p = Kc + ((size_t)s * NKV + kvh) * HD;
        float x0 = p[i], x1 = p[i + 64];
        float y0 = x0 * cs - x1 * sn;
        float y1 = x1 * cs + x0 * sn;
        size_t o0 = ((size_t)kvh * HD + i) * S_LEN + s;
        size_t o1 = ((size_t)kvh * HD + i + 64) * S_LEN + s;
        __half h0 = __float2half_rn(y0);
        khiT[o0] = h0;
        kloT[o0] = __float2half_rn(y0 - __half2float(h0));
        __half h1 = __float2half_rn(y1);
        khiT[o1] = h1;
        kloT[o1] = __float2half_rn(y1 - __half2float(h1));
    } else {
        split4_at(V, vhi, vlo, idx - R1);
    }
}

// ---------------- HMMA GEMM: 3-stage cp.async pipeline, fp16 split ----------
// Tile 128x128, BK=32, 8 warps. ALO=1: 3-term (hihi+hilo+lohi); ALO=0: 2-term
// (A residual dropped; Alo never read). One __syncthreads per chunk.
template <int FUSED, int ALO>
__global__ __launch_bounds__(256)
void gemm_hmma_kernel(const __half* __restrict__ Ahi, const __half* __restrict__ Alo,
                      const __half* __restrict__ Bhi0, const __half* __restrict__ Blo0,
                      const __half* __restrict__ Bhi1, const __half* __restrict__ Blo1,
                      const __half* __restrict__ Bhi2, const __half* __restrict__ Blo2,
                      float* __restrict__ C0, float* __restrict__ C1,
                      float* __restrict__ C2, int K, int N0) {
    extern __shared__ char smem[];
    uint32_t sb = smem_u32(smem);
    // stage = 32KB: A_hi[0,8K) A_lo[8K,16K) B_hi[16K,24K) B_lo[24K,32K); 3 stages

    int tid = threadIdx.x, wid = tid >> 5, lane = tid & 31;
    int bn = blockIdx.x, bm = blockIdx.y;
    int wm = wid & 1, wn = wid >> 1;

    const __half* Bhi = Bhi0;
    const __half* Blo = Blo0;
    float* C = C0;
    int ldn = N0, bcol = bn * 128;
    if (FUSED) {
        if (bn >= 28 && bn < 32) {
            Bhi = Bhi1; Blo = Blo1; C = C1; ldn = NKV * HD; bcol = (bn - 28) * 128;
        } else if (bn >= 32) {
            Bhi = Bhi2; Blo = Blo2; C = C2; ldn = NKV * HD; bcol = (bn - 32) * 128;
        }
    }

    int ar0 = tid >> 2, ac0 = tid & 3;
    int ar1 = (tid + 256) >> 2, ac1 = tid & 3;
    int br0 = tid >> 4, bc0 = tid & 15;
    int br1 = (tid + 256) >> 4, bc1 = tid & 15;
    uint32_t a_d0 = (uint32_t)(ar0 * 64 + ((ac0 ^ ((ar0 >> 1) & 3)) << 4));
    uint32_t a_d1 = (uint32_t)(ar1 * 64 + ((ac1 ^ ((ar1 >> 1) & 3)) << 4));
    uint32_t b_d0 = (uint32_t)(br0 * 256 + ((bc0 ^ (br0 & 7)) << 4));
    uint32_t b_d1 = (uint32_t)(br1 * 256 + ((bc1 ^ (br1 & 7)) << 4));

    const int nch = K >> 5;

#define LOAD_STAGE(stg, ch) do {                                              \
    uint32_t base = sb + (uint32_t)(stg) * 32768u;                            \
    const __half* ah = Ahi + (size_t)(bm * 128) * K + (ch) * 32;              \
    CPASYNC16(base + a_d0,          ah + (size_t)ar0 * K + ac0 * 8);          \
    CPASYNC16(base + a_d1,          ah + (size_t)ar1 * K + ac1 * 8);          \
    if (ALO) {                                                                \
        const __half* al = Alo + (size_t)(bm * 128) * K + (ch) * 32;          \
        CPASYNC16(base + 8192 + a_d0, al + (size_t)ar0 * K + ac0 * 8);        \
        CPASYNC16(base + 8192 + a_d1, al + (size_t)ar1 * K + ac1 * 8);        \
    }                                                                         \
    const __half* bh = Bhi + (size_t)((ch) * 32) * ldn + bcol;                \
    const __half* bl = Blo + (size_t)((ch) * 32) * ldn + bcol;                \
    CPASYNC16(base + 16384 + b_d0,  bh + (size_t)br0 * ldn + bc0 * 8);        \
    CPASYNC16(base + 16384 + b_d1,  bh + (size_t)br1 * ldn + bc1 * 8);        \
    CPASYNC16(base + 24576 + b_d0,  bl + (size_t)br0 * ldn + bc0 * 8);        \
    CPASYNC16(base + 24576 + b_d1,  bl + (size_t)br1 * ldn + bc1 * 8);        \
} while (0)

    int mat = lane >> 3;
    int arb = wm * 64 + ((mat & 1) << 3) + (lane & 7);
    int asw = (arb >> 1) & 3;
    int bkb = ((mat & 1) << 3) + (lane & 7);
    int bsw = lane & 7;
    int bnc = wn * 4 + (mat >> 1);

    float acc[4][4][4];
#pragma unroll
    for (int i = 0; i < 4; i++)
#pragma unroll
        for (int j = 0; j < 4; j++)
#pragma unroll
            for (int q = 0; q < 4; q++) acc[i][j][q] = 0.f;

    LOAD_STAGE(0, 0);
    CP_COMMIT();
    if (nch > 1) {
        LOAD_STAGE(1, 1);
        CP_COMMIT();
    }

    int stg = 0;
    for (int ch = 0; ch < nch; ch++) {
        if (ch + 1 < nch) { CP_WAIT1(); } else { CP_WAIT0(); }
        __syncthreads();
        if (ch + 2 < nch) {
            int ns = stg + 2;
            if (ns >= 3) ns -= 3;
            LOAD_STAGE(ns, ch + 2);
            CP_COMMIT();
        }

        uint32_t Ab_hi = sb + (uint32_t)stg * 32768u;
        uint32_t Ab_lo = Ab_hi + 8192;
        uint32_t Bb_hi = Ab_hi + 16384;
        uint32_t Bb_lo = Ab_hi + 24576;

#pragma unroll
        for (int kh = 0; kh < 2; kh++) {
            uint32_t ac = (uint32_t)(((kh * 2 + (mat >> 1)) ^ asw) << 4);
            uint32_t a_hi[4][4], a_lo[4][4];
#pragma unroll
            for (int mt = 0; mt < 4; mt++) {
                uint32_t ro = (uint32_t)((arb + mt * 16) * 64);
                ldsm_x4(a_hi[mt], Ab_hi + ro + ac);
                if (ALO) ldsm_x4(a_lo[mt], Ab_lo + ro + ac);
            }
            uint32_t bro = (uint32_t)((kh * 16 + bkb) * 256);
            uint32_t b_hi[2][4], b_lo[2][4];
#pragma unroll
            for (int p = 0; p < 2; p++) {
                uint32_t co = (uint32_t)((((bnc + p * 2)) ^ bsw) << 4);
                ldsm_x4t(b_hi[p], Bb_hi + bro + co);
                ldsm_x4t(b_lo[p], Bb_lo + bro + co);
            }
#pragma unroll
            for (int mt = 0; mt < 4; mt++)
#pragma unroll
                for (int p = 0; p < 2; p++) {
                    mma16816(acc[mt][p * 2],     a_hi[mt], b_hi[p][0], b_hi[p][1]);
                    mma16816(acc[mt][p * 2 + 1], a_hi[mt], b_hi[p][2], b_hi[p][3]);
                    mma16816(acc[mt][p * 2],     a_hi[mt], b_lo[p][0], b_lo[p][1]);
                    mma16816(acc[mt][p * 2 + 1], a_hi[mt], b_lo[p][2], b_lo[p][3]);
                    if (ALO) {
                        mma16816(acc[mt][p * 2],     a_lo[mt], b_hi[p][0], b_hi[p][1]);
                        mma16816(acc[mt][p * 2 + 1], a_lo[mt], b_hi[p][2], b_hi[p][3]);
                    }
                }
        }
        if (++stg == 3) stg = 0;
    }
#undef LOAD_STAGE

#pragma unroll
    for (int mt = 0; mt < 4; mt++) {
        int row = bm * 128 + wm * 64 + mt * 16 + (lane >> 2);
#pragma unroll
        for (int nt = 0; nt < 4; nt++) {
            int col = bcol + wn * 32 + (nt >> 1) * 16 + (nt & 1) * 8 + (lane & 3) * 2;
            *(float2*)(C + (size_t)row * ldn + col) =
                make_float2(acc[mt][nt][0], acc[mt][nt][1]);
            *(float2*)(C + (size_t)(row + 8) * ldn + col) =
                make_float2(acc[mt][nt][2], acc[mt][nt][3]);
        }
    }
}

// ---------------- HMMA flash attention: 3-term QK and PV --------------------
// Output written as fp16 hi only (O-proj is 2-term on the A side).
__global__ __launch_bounds__(256, 1)
void flash_hmma_kernel(const __half* __restrict__ Qhi, const __half* __restrict__ Qlo,
                       const __half* __restrict__ KhiT, const __half* __restrict__ KloT,
                       const __half* __restrict__ Vhi, const __half* __restrict__ Vlo,
                       const int* __restrict__ amask,
                       __half* __restrict__ Ahi) {
    extern __shared__ char sm[];
    uint32_t sb = smem_u32(sm);
    float* sbias = (float*)(sm + 196608);

    int tid = threadIdx.x, wq = tid >> 5, lane = tid & 31;
    int mat = lane >> 3, l7 = lane & 7, qd = lane >> 2, l3 = lane & 3;
    int qb = (int)(gridDim.x - 1 - blockIdx.x);
    int h = blockIdx.y, kvh = h / REP;

    {
        const __half* qh = Qhi + ((size_t)(qb * 128) * NH + h) * HD;
        const __half* ql = Qlo + ((size_t)(qb * 128) * NH + h) * HD;
#pragma unroll
        for (int i = 0; i < 8; i++) {
            int idx = tid + i * 256;
            int row = idx >> 4, ch = idx & 15;
            uint32_t dst = sb + (uint32_t)(row * 256 + ((ch ^ (row & 7)) << 4));
            CPASYNC16(dst,         qh + (size_t)row * NHD + ch * 8);
            CPASYNC16(dst + 32768, ql + (size_t)row * NHD + ch * 8);
        }
    }

    auto load_kv = [&](int stage, int kb) {
        uint32_t base = sb + 65536u + (uint32_t)stage * 65536u;
        const __half* kh_ = KhiT + (size_t)kvh * HD * S_LEN + kb * 64;
        const __half* kl_ = KloT + (size_t)kvh * HD * S_LEN + kb * 64;
#pragma unroll
        for (int i = 0; i < 4; i++) {
            int idx = tid + i * 256;
            int row = idx >> 3, ch = idx & 7;
            uint32_t dst = base + (uint32_t)(row * 128 + ((ch ^ (row & 7)) << 4));
            CPASYNC16(dst,         kh_ + (size_t)row * S_LEN + ch * 8);
            CPASYNC16(dst + 16384, kl_ + (size_t)row * S_LEN + ch * 8);
        }
        const __half* vh_ = Vhi + ((size_t)(kb * 64) * NKV + kvh) * HD;
        const __half* vl_ = Vlo + ((size_t)(kb * 64) * NKV + kvh) * HD;
#pragma unroll
        for (int i = 0; i < 4; i++) {
            int idx = tid + i * 256;
            int row = idx >> 4, ch = idx & 15;
            uint32_t dst = base + 32768u + (uint32_t)(row * 256 + ((ch ^ (row & 7)) << 4));
            CPASYNC16(dst,         vh_ + (size_t)row * NKV * HD + ch * 8);
            CPASYNC16(dst + 16384, vl_ + (size_t)row * NKV * HD + ch * 8);
        }
    };

    load_kv(0, 0);
    CP_COMMIT();

    float o[16][4];
#pragma unroll
    for (int i = 0; i < 16; i++)
#pragma unroll
        for (int j = 0; j < 4; j++) o[i][j] = 0.f;
    float m0 = -1e30f, m1 = -1e30f, l0 = 0.f, l1 = 0.f;

    int kbmax = 2 * qb + 1;
    int r0g = qb * 128 + wq * 16 + qd, r1g = r0g + 8;
    int arow = wq * 16 + ((mat & 1) << 3) + l7;
    int brow0 = ((mat & 1) << 3) + l7;

    for (int kb = 0; kb <= kbmax; kb++) {
        if (kb < kbmax) {
            load_kv((kb + 1) & 1, kb + 1);
            CP_COMMIT();
            CP_WAIT1();
        } else {
            CP_WAIT0();
        }
        if (tid < 64) sbias[tid] = amask[kb * 64 + tid] ? 0.f : -1e30f;
        __syncthreads();

        uint32_t Kb = sb + 65536u + (uint32_t)(kb & 1) * 65536u;
        uint32_t Vb = Kb + 32768u;

        float s[8][4];
#pragma unroll
        for (int i = 0; i < 8; i++)
#pragma unroll
            for (int j = 0; j < 4; j++) s[i][j] = 0.f;

#pragma unroll
        for (int kh2 = 0; kh2 < 8; kh2++) {
            uint32_t a_hi[4], a_lo[4];
            int ach = kh2 * 2 + (mat >> 1);
            uint32_t aaddr = sb + (uint32_t)(arow * 256 + ((ach ^ (arow & 7)) << 4));
            ldsm_x4(a_hi, aaddr);
            ldsm_x4(a_lo, aaddr + 32768);
            int brow = kh2 * 16 + brow0;
#pragma unroll
            for (int hf = 0; hf < 2; hf++) {
                uint32_t b_hi[2][4], b_lo[2][4];
#pragma unroll
                for (int p = 0; p < 2; p++) {
                    int bch = (hf * 2 + p) * 2 + (mat >> 1);
                    uint32_t baddr = Kb + (uint32_t)(brow * 128 + ((bch ^ (brow & 7)) << 4));
                    ldsm_x4t(b_hi[p], baddr);
                    ldsm_x4t(b_lo[p], baddr + 16384);
                }
#pragma unroll
                for (int p = 0; p < 2; p++)
#pragma unroll
                    for (int e = 0; e < 2; e++) {
                        int nt = hf * 4 + p * 2 + e;
                        mma16816(s[nt], a_hi, b_hi[p][e * 2], b_hi[p][e * 2 + 1]);
                        mma16816(s[nt], a_hi, b_lo[p][e * 2], b_lo[p][e * 2 + 1]);
                        mma16816(s[nt], a_lo, b_hi[p][e * 2], b_hi[p][e * 2 + 1]);
                    }
            }
        }

#pragma unroll
        for (int nt = 0; nt < 8; nt++) {
            int c = nt * 8 + 2 * l3;
            float b0 = sbias[c], b1 = sbias[c + 1];
            s[nt][0] += b0; s[nt][1] += b1; s[nt][2] += b0; s[nt][3] += b1;
        }
        if (kb >= 2 * qb) {
            int cbase = kb * 64 + 2 * l3;
#pragma unroll
            for (int nt = 0; nt < 8; nt++) {
                int c0 = cbase + nt * 8, c1 = c0 + 1;
                if (c0 > r0g) s[nt][0] = -1e30f;
                if (c1 > r0g) s[nt][1] = -1e30f;
                if (c0 > r1g) s[nt][2] = -1e30f;
                if (c1 > r1g) s[nt][3] = -1e30f;
            }
        }

        float mx0 = -1e30f, mx1 = -1e30f;
#pragma unroll
        for (int nt = 0; nt < 8; nt++) {
            mx0 = fmaxf(mx0, fmaxf(s[nt][0], s[nt][1]));
            mx1 = fmaxf(mx1, fmaxf(s[nt][2], s[nt][3]));
        }
        mx0 = fmaxf(mx0, __shfl_xor_sync(0xffffffffu, mx0, 1));
        mx0 = fmaxf(mx0, __shfl_xor_sync(0xffffffffu, mx0, 2));
        mx1 = fmaxf(mx1, __shfl_xor_sync(0xffffffffu, mx1, 1));
        mx1 = fmaxf(mx1, __shfl_xor_sync(0xffffffffu, mx1, 2));
        float mn0 = fmaxf(m0, mx0), mn1 = fmaxf(m1, mx1);
        float al0 = __expf(m0 - mn0), al1 = __expf(m1 - mn1);
        m0 = mn0; m1 = mn1;
        float rs0 = 0.f, rs1 = 0.f;
#pragma unroll
        for (int nt = 0; nt < 8; nt++) {
            s[nt][0] = __expf(s[nt][0] - mn0); rs0 += s[nt][0];
            s[nt][1] = __expf(s[nt][1] - mn0); rs0 += s[nt][1];
            s[nt][2] = __expf(s[nt][2] - mn1); rs1 += s[nt][2];
            s[nt][3] = __expf(s[nt][3] - mn1); rs1 += s[nt][3];
        }
        rs0 += __shfl_xor_sync(0xffffffffu, rs0, 1);
        rs0 += __shfl_xor_sync(0xffffffffu, rs0, 2);
        rs1 += __shfl_xor_sync(0xffffffffu, rs1, 1);
        rs1 += __shfl_xor_sync(0xffffffffu, rs1, 2);
        l0 = l0 * al0 + rs0;
        l1 = l1 * al1 + rs1;
#pragma unroll
        for (int nt = 0; nt < 16; nt++) {
            o[nt][0] *= al0; o[nt][1] *= al0;
            o[nt][2] *= al1; o[nt][3] *= al1;
        }

#pragma unroll
        for (int j = 0; j < 4; j++) {
            uint32_t phi[4], plo[4];
            split2(s[2 * j][0],     s[2 * j][1],     phi[0], plo[0]);
            split2(s[2 * j][2],     s[2 * j][3],     phi[1], plo[1]);
            split2(s[2 * j + 1][0], s[2 * j + 1][1], phi[2], plo[2]);
            split2(s[2 * j + 1][2], s[2 * j + 1][3], phi[3], plo[3]);
            int vrow = j * 16 + ((mat & 1) << 3) + l7;
#pragma unroll
            for (int nb = 0; nb < 8; nb++) {
                uint32_t v_hi[4], v_lo[4];
                int vch = nb * 2 + (mat >> 1);
                uint32_t vaddr = Vb + (uint32_t)(vrow * 256 + ((vch ^ (vrow & 7)) << 4));
                ldsm_x4t(v_hi, vaddr);
                ldsm_x4t(v_lo, vaddr + 16384);
#pragma unroll
                for (int e = 0; e < 2; e++) {
                    int nt = nb * 2 + e;
                    mma16816(o[nt], phi, v_hi[e * 2], v_hi[e * 2 + 1]);
                    mma16816(o[nt], phi, v_lo[e * 2], v_lo[e * 2 + 1]);
                    mma16816(o[nt], plo, v_hi[e * 2], v_hi[e * 2 + 1]);
                }
            }
        }
        __syncthreads();
    }

    // normalize + store (fp16 hi only)
    float inv0 = 1.f / l0, inv1 = 1.f / l1;
    size_t ro0 = (size_t)r0g * NHD + h * HD + 2 * l3;
    size_t ro1 = (size_t)r1g * NHD + h * HD + 2 * l3;
#pragma unroll
    for (int nt = 0; nt < 16; nt++) {
        *(__half2*)(Ahi + ro0 + nt * 8) =
            __floats2half2_rn(o[nt][0] * inv0, o[nt][1] * inv0);
        *(__half2*)(Ahi + ro1 + nt * 8) =
            __floats2half2_rn(o[nt][2] * inv1, o[nt][3] * inv1);
    }
}

// ---------------- launcher ---------------------------------------------------
extern "C" void kernel_launch(void* const* d_in, const int* in_sizes, int n_in,
                              void* d_out, int out_size) {
    const float* x     = (const float*)d_in[0];
    const int*   amask = (const int*)  d_in[1];
    const int*   pos   = (const int*)  d_in[2];
    const float* Wq    = (const float*)d_in[3];
    const float* Wk    = (const float*)d_in[4];
    const float* Wv    = (const float*)d_in[5];
    const float* Wo    = (const float*)d_in[6];
    float* out = (float*)d_out;

    float *qp, *kp, *vp;
    cudaGetSymbolAddress((void**)&qp, g_q);
    cudaGetSymbolAddress((void**)&kp, g_k);
    cudaGetSymbolAddress((void**)&vp, g_v);
    __half *xh, *xl, *wqh, *wql, *wkh, *wkl, *wvh, *wvl, *woh, *wol, *ah;
    __half *qhi, *qlo, *khiT, *kloT, *vhi, *vlo;
    cudaGetSymbolAddress((void**)&xh,  g_x_hi);  cudaGetSymbolAddress((void**)&xl,  g_x_lo);
    cudaGetSymbolAddress((void**)&wqh, g_wq_hi); cudaGetSymbolAddress((void**)&wql, g_wq_lo);
    cudaGetSymbolAddress((void**)&wkh, g_wk_hi); cudaGetSymbolAddress((void**)&wkl, g_wk_lo);
    cudaGetSymbolAddress((void**)&wvh, g_wv_hi); cudaGetSymbolAddress((void**)&wvl, g_wv_lo);
    cudaGetSymbolAddress((void**)&woh, g_wo_hi); cudaGetSymbolAddress((void**)&wol, g_wo_lo);
    cudaGetSymbolAddress((void**)&ah,  g_a_hi);
    cudaGetSymbolAddress((void**)&qhi, g_qhi);   cudaGetSymbolAddress((void**)&qlo, g_qlo);
    cudaGetSymbolAddress((void**)&khiT, g_khiT); cudaGetSymbolAddress((void**)&kloT, g_kloT);
    cudaGetSymbolAddress((void**)&vhi, g_vhi);   cudaGetSymbolAddress((void**)&vlo, g_vlo);

    // 0) fused split of x + all weights
    const int SPLIT_TOT = (S_LEN * HID + HID * NH * HD + 2 * HID * NKV * HD
                           + NH * HD * HID) / 4;
    split_all_kernel<<<(SPLIT_TOT + 255) / 256, 256>>>(
        x, Wq, Wk, Wv, Wo, xh, xl, wqh, wql, wkh, wkl, wvh, wvl, woh, wol);

    // 1) RoPE table
    build_rope_kernel<<<(S_LEN * 64 + 255) / 256, 256>>>(pos);

    // 2) fused QKV projection (HMMA, 3-term, 3-stage pipeline)
    const int gemm_smem = 98304;
    cudaFuncSetAttribute(gemm_hmma_kernel<1, 1>,
                         cudaFuncAttributeMaxDynamicSharedMemorySize, gemm_smem);
    cudaFuncSetAttribute(gemm_hmma_kernel<0, 0>,
                         cudaFuncAttributeMaxDynamicSharedMemorySize, gemm_smem);
    gemm_hmma_kernel<1, 1><<<dim3(36, 16), 256, gemm_smem>>>(
        xh, xl, wqh, wql, wkh, wkl, wvh, wvl, qp, kp, vp, HID, NH * HD);

    // 3) fused RoPE+split (Q, K^T) + V split
    const int PREP_TOT = S_LEN * NH * 64 + S_LEN * NKV * 64 + S_LEN * NKV * HD / 4;
    prep_attention_kernel<<<(PREP_TOT + 255) / 256, 256>>>(
        qp, kp, vp, qhi, qlo, khiT, kloT, vhi, vlo);

    // 4) HMMA flash attention -> fp16 hi output
    const int flash_smem = 196864;
    cudaFuncSetAttribute(flash_hmma_kernel,
                         cudaFuncAttributeMaxDynamicSharedMemorySize, flash_smem);
    flash_hmma_kernel<<<dim3(S_LEN / 128, NH), 256, flash_smem>>>(
        qhi, qlo, khiT, kloT, vhi, vlo, amask, ah);

    // 5) O projection (HMMA, 2-term: A residual dropped) -> final output
    gemm_hmma_kernel<0, 0><<<dim3(28, 16), 256, gemm_smem>>>(
        ah, nullptr, woh, wol, nullptr, nullptr, nullptr, nullptr,
        out, nullptr, nullptr, HID, HID);
}